// round 10
// baseline (speedup 1.0000x reference)
#include <cuda_runtime.h>
#include <cuda_bf16.h>
#include <cstdint>
#include <math.h>

#define NN    50000
#define EE    800000
#define ETOTE 850000
#define BB    64
#define FIN   128
#define POSD  16
#define ENHD  144
#define HH    4
#define CCD   64
#define HCC   256
#define OUTD  128
#define BNEPS 1e-5f

// ---------------- scratch ----------------
__device__ float  g_h0[NN * ENHD];
__device__ float  g_hl[NN * HCC];
__device__ float  g_hagg[NN * HCC];
__device__ __nv_bfloat16 g_abf[(NN + 256) * 768];
__device__ __nv_bfloat16 g_wbf[256 * 768];
__device__ float  g_as[NN * HH];
__device__ float  g_ad[NN * HH];
__device__ int    g_counts[BB];
__device__ int    g_starts[BB];
__device__ int    g_gridsz[BB];
__device__ float  g_denomv[BB];
__device__ int    g_indeg[NN];
__device__ int    g_rowstart[NN + 1];
__device__ int    g_fillpos[NN];
__device__ int    g_csrsrc[ETOTE];
__device__ int    g_bsum[256];
__device__ double g_sum[HCC];
__device__ double g_sumsq[HCC];
__device__ float  g_mean[HCC];
__device__ float  g_rstd[HCC];
__device__ float  g_pooled[BB * HCC];

// ---------------- graph meta ----------------
__global__ void k_prep_zero() {
    int i = blockIdx.x * blockDim.x + threadIdx.x;
    if (i < NN) g_indeg[i] = 0;
    if (i < BB) g_counts[i] = 0;
    if (i < HCC) { g_sum[i] = 0.0; g_sumsq[i] = 0.0; }
    if (i < BB * HCC) g_pooled[i] = 0.f;
}

__global__ void k_count_nodes(const int* __restrict__ batch) {
    int i = blockIdx.x * blockDim.x + threadIdx.x;
    if (i < NN) atomicAdd(&g_counts[batch[i]], 1);
}

__global__ void k_graph_meta() {
    int b = threadIdx.x;
    if (b >= BB) return;
    int st = 0;
    for (int j = 0; j < b; j++) st += g_counts[j];
    g_starts[b] = st;
    int c = g_counts[b];
    int g = (int)ceil(sqrt((double)c));
    g_gridsz[b] = g;
    int d = g - 1; if (d < 1) d = 1;
    g_denomv[b] = (float)d;
}

__global__ void k_build_h0(const float* __restrict__ x, const int* __restrict__ batch,
                           const float* __restrict__ Wpos, const float* __restrict__ bpos) {
    int tid = blockIdx.x * blockDim.x + threadIdx.x;
    if (tid >= NN * (ENHD / 4)) return;
    int n = tid / (ENHD / 4);
    int f4 = tid - n * (ENHD / 4);
    float4 v;
    if (f4 < FIN / 4) {
        v = ((const float4*)x)[(size_t)n * (FIN / 4) + f4];
    } else {
        int b = batch[n];
        int i = n - g_starts[b];
        int g = g_gridsz[b];
        float denom = g_denomv[b];
        int row = i / g;
        int col = i - row * g;
        float p0 = (float)row / denom;
        float p1 = (float)col / denom;
        int j = (f4 - FIN / 4) * 4;
        v.x = p0 * Wpos[j + 0] + p1 * Wpos[POSD + j + 0] + bpos[j + 0];
        v.y = p0 * Wpos[j + 1] + p1 * Wpos[POSD + j + 1] + bpos[j + 1];
        v.z = p0 * Wpos[j + 2] + p1 * Wpos[POSD + j + 2] + bpos[j + 2];
        v.w = p0 * Wpos[j + 3] + p1 * Wpos[POSD + j + 3] + bpos[j + 3];
    }
    ((float4*)g_h0)[tid] = v;
}

// ---------------- CSR by destination ----------------
__global__ void k_edge_count(const int* __restrict__ ei) {
    int e = blockIdx.x * blockDim.x + threadIdx.x;
    if (e >= ETOTE) return;
    int dst = (e < EE) ? ei[EE + e] : (e - EE);
    atomicAdd(&g_indeg[dst], 1);
}

__global__ void k_scanA() {
    __shared__ int s[256];
    int i = blockIdx.x * 256 + threadIdx.x;
    int v = (i < NN) ? g_indeg[i] : 0;
    s[threadIdx.x] = v;
    __syncthreads();
    for (int off = 1; off < 256; off <<= 1) {
        int t = (threadIdx.x >= off) ? s[threadIdx.x - off] : 0;
        __syncthreads();
        s[threadIdx.x] += t;
        __syncthreads();
    }
    if (i < NN) g_rowstart[i] = s[threadIdx.x] - v;
    if (threadIdx.x == 255) g_bsum[blockIdx.x] = s[255];
}

__global__ void k_scanB() {
    __shared__ int s[256];
    int t = threadIdx.x;
    int v = (t < 196) ? g_bsum[t] : 0;
    s[t] = v;
    __syncthreads();
    for (int off = 1; off < 256; off <<= 1) {
        int u = (t >= off) ? s[t - off] : 0;
        __syncthreads();
        s[t] += u;
        __syncthreads();
    }
    if (t < 196) g_bsum[t] = s[t] - v;
}

__global__ void k_scanC() {
    int i = blockIdx.x * 256 + threadIdx.x;
    if (i < NN) {
        int rs = g_rowstart[i] + g_bsum[blockIdx.x];
        g_rowstart[i] = rs;
        g_fillpos[i] = rs;
    }
    if (i == 0) g_rowstart[NN] = ETOTE;
}

__global__ void k_edge_fill(const int* __restrict__ ei) {
    int e = blockIdx.x * blockDim.x + threadIdx.x;
    if (e >= ETOTE) return;
    int src, dst;
    if (e < EE) { src = ei[e]; dst = ei[EE + e]; }
    else        { src = e - EE; dst = src; }
    int p = atomicAdd(&g_fillpos[dst], 1);
    g_csrsrc[p] = src;
}

// ---------------- bf16x3 split conversion (vectorized) ----------------
__global__ void k_convA(const float* __restrict__ A, int K, int Kp) {
    int idx = blockIdx.x * blockDim.x + threadIdx.x;      // over NN*K/4
    if (idx >= NN * (K / 4)) return;
    int n = idx / (K / 4), k = (idx - n * (K / 4)) * 4;
    float4 x = ((const float4*)A)[idx];
    __nv_bfloat162 h0 = __float22bfloat162_rn(make_float2(x.x, x.y));
    __nv_bfloat162 h1 = __float22bfloat162_rn(make_float2(x.z, x.w));
    float2 hlo0 = __bfloat1622float2(h0), hlo1 = __bfloat1622float2(h1);
    __nv_bfloat162 l0 = __float22bfloat162_rn(make_float2(x.x - hlo0.x, x.y - hlo0.y));
    __nv_bfloat162 l1 = __float22bfloat162_rn(make_float2(x.z - hlo1.x, x.w - hlo1.y));
    size_t base = (size_t)n * Kp + k;
    *(__nv_bfloat162*)(g_abf + base) = h0;
    *(__nv_bfloat162*)(g_abf + base + 2) = h1;
    *(__nv_bfloat162*)(g_abf + base + K) = l0;
    *(__nv_bfloat162*)(g_abf + base + K + 2) = l1;
    *(__nv_bfloat162*)(g_abf + base + 2 * K) = h0;
    *(__nv_bfloat162*)(g_abf + base + 2 * K + 2) = h1;
}

// layer-2 A conversion with fused BatchNorm + ELU
__global__ void k_convA_bn(const float* __restrict__ gamma, const float* __restrict__ beta) {
    int idx = blockIdx.x * blockDim.x + threadIdx.x;      // over NN*64
    if (idx >= NN * 64) return;
    int n = idx >> 6, k = (idx & 63) * 4;
    float4 v = ((const float4*)g_hagg)[idx];
    float y0 = gamma[k + 0] * (v.x - g_mean[k + 0]) * g_rstd[k + 0] + beta[k + 0];
    float y1 = gamma[k + 1] * (v.y - g_mean[k + 1]) * g_rstd[k + 1] + beta[k + 1];
    float y2 = gamma[k + 2] * (v.z - g_mean[k + 2]) * g_rstd[k + 2] + beta[k + 2];
    float y3 = gamma[k + 3] * (v.w - g_mean[k + 3]) * g_rstd[k + 3] + beta[k + 3];
    y0 = (y0 > 0.f) ? y0 : expm1f(y0);
    y1 = (y1 > 0.f) ? y1 : expm1f(y1);
    y2 = (y2 > 0.f) ? y2 : expm1f(y2);
    y3 = (y3 > 0.f) ? y3 : expm1f(y3);
    __nv_bfloat162 h0 = __float22bfloat162_rn(make_float2(y0, y1));
    __nv_bfloat162 h1 = __float22bfloat162_rn(make_float2(y2, y3));
    float2 f0 = __bfloat1622float2(h0), f1 = __bfloat1622float2(h1);
    __nv_bfloat162 l0 = __float22bfloat162_rn(make_float2(y0 - f0.x, y1 - f0.y));
    __nv_bfloat162 l1 = __float22bfloat162_rn(make_float2(y2 - f1.x, y3 - f1.y));
    size_t base = (size_t)n * 768 + k;
    *(__nv_bfloat162*)(g_abf + base) = h0;
    *(__nv_bfloat162*)(g_abf + base + 2) = h1;
    *(__nv_bfloat162*)(g_abf + base + 256) = l0;
    *(__nv_bfloat162*)(g_abf + base + 258) = l1;
    *(__nv_bfloat162*)(g_abf + base + 512) = h0;
    *(__nv_bfloat162*)(g_abf + base + 514) = h1;
}

// W' transposed to [n][k']: [W_hi | W_hi | W_lo], pad zero
__global__ void k_convW(const float* __restrict__ W, int K, int Kp) {
    int idx = blockIdx.x * blockDim.x + threadIdx.x;
    if (idx >= HCC * Kp) return;
    int n = idx / Kp, k = idx - n * Kp;
    __nv_bfloat16 v;
    if (k < K) {
        v = __float2bfloat16(W[(size_t)k * HCC + n]);
    } else if (k < 2 * K) {
        v = __float2bfloat16(W[(size_t)(k - K) * HCC + n]);
    } else if (k < 3 * K) {
        float x = W[(size_t)(k - 2 * K) * HCC + n];
        __nv_bfloat16 hi = __float2bfloat16(x);
        v = __float2bfloat16(x - __bfloat162float(hi));
    } else {
        v = __float2bfloat16(0.f);
    }
    g_wbf[idx] = v;
}

// ---------------- HMMA GEMM: g_hl[M,256] = A'[M,KP] @ W'^T ----------------
template<int KP>
__global__ void __launch_bounds__(256) k_gemm_mma() {
    __shared__ __nv_bfloat16 As[2][128][40];
    __shared__ __nv_bfloat16 Bs[2][128][40];
    const int tid = threadIdx.x;
    const int lane = tid & 31, wid = tid >> 5;
    const int wm = wid & 1, wn = wid >> 1;
    const int g = lane >> 2, tq = lane & 3;
    const int m0 = blockIdx.x * 128, n0 = blockIdx.y * 128;

    float acc[4][4][4];
    #pragma unroll
    for (int a = 0; a < 4; a++)
        #pragma unroll
        for (int b = 0; b < 4; b++)
            #pragma unroll
            for (int c = 0; c < 4; c++) acc[a][b][c] = 0.f;

    const int lr = tid >> 2;
    const int lc = tid & 3;
    const __nv_bfloat16* gA = g_abf + (size_t)m0 * KP;
    const __nv_bfloat16* gB = g_wbf + (size_t)n0 * KP;

    uint4 pa[2], pb[2];
    auto ld_chunk = [&](int k0) {
        #pragma unroll
        for (int i = 0; i < 2; i++) {
            int row = lr + i * 64;
            pa[i] = *(const uint4*)(gA + (size_t)row * KP + k0 + lc * 8);
            pb[i] = *(const uint4*)(gB + (size_t)row * KP + k0 + lc * 8);
        }
    };
    auto st_chunk = [&](int b) {
        #pragma unroll
        for (int i = 0; i < 2; i++) {
            int row = lr + i * 64;
            *(uint4*)&As[b][row][lc * 8] = pa[i];
            *(uint4*)&Bs[b][row][lc * 8] = pb[i];
        }
    };

    ld_chunk(0);
    st_chunk(0);
    __syncthreads();

    const int C = KP / 32;
    for (int c = 0; c < C; c++) {
        int cur = c & 1;
        if (c + 1 < C) ld_chunk((c + 1) * 32);
        #pragma unroll
        for (int ks = 0; ks < 2; ks++) {
            uint32_t af[4][4], bf[4][2];
            #pragma unroll
            for (int mt = 0; mt < 4; mt++) {
                int r = wm * 64 + mt * 16 + g;
                int cbase = ks * 16 + tq * 2;
                af[mt][0] = *(const uint32_t*)&As[cur][r][cbase];
                af[mt][1] = *(const uint32_t*)&As[cur][r + 8][cbase];
                af[mt][2] = *(const uint32_t*)&As[cur][r][cbase + 8];
                af[mt][3] = *(const uint32_t*)&As[cur][r + 8][cbase + 8];
            }
            #pragma unroll
            for (int nt = 0; nt < 4; nt++) {
                int r = wn * 32 + nt * 8 + g;
                int cbase = ks * 16 + tq * 2;
                bf[nt][0] = *(const uint32_t*)&Bs[cur][r][cbase];
                bf[nt][1] = *(const uint32_t*)&Bs[cur][r][cbase + 8];
            }
            #pragma unroll
            for (int mt = 0; mt < 4; mt++)
                #pragma unroll
                for (int nt = 0; nt < 4; nt++)
                    asm volatile(
                        "mma.sync.aligned.m16n8k16.row.col.f32.bf16.bf16.f32 "
                        "{%0,%1,%2,%3}, {%4,%5,%6,%7}, {%8,%9}, {%0,%1,%2,%3};\n"
                        : "+f"(acc[mt][nt][0]), "+f"(acc[mt][nt][1]),
                          "+f"(acc[mt][nt][2]), "+f"(acc[mt][nt][3])
                        : "r"(af[mt][0]), "r"(af[mt][1]), "r"(af[mt][2]), "r"(af[mt][3]),
                          "r"(bf[nt][0]), "r"(bf[nt][1]));
        }
        if (c + 1 < C) st_chunk(1 - cur);
        __syncthreads();
    }

    #pragma unroll
    for (int mt = 0; mt < 4; mt++) {
        int r0 = m0 + wm * 64 + mt * 16 + g;
        #pragma unroll
        for (int nt = 0; nt < 4; nt++) {
            int cc = n0 + wn * 32 + nt * 8 + tq * 2;
            if (r0 < NN)
                *(float2*)&g_hl[(size_t)r0 * HCC + cc] =
                    make_float2(acc[mt][nt][0], acc[mt][nt][1]);
            if (r0 + 8 < NN)
                *(float2*)&g_hl[(size_t)(r0 + 8) * HCC + cc] =
                    make_float2(acc[mt][nt][2], acc[mt][nt][3]);
        }
    }
}

// ---------------- attention logits ----------------
__global__ void k_alpha(const float* __restrict__ asrc, const float* __restrict__ adst) {
    int gid = blockIdx.x * blockDim.x + threadIdx.x;
    int warp = gid >> 5;
    int lane = gid & 31;
    if (warp >= NN * HH) return;
    int n = warp >> 2;
    int h = warp & 3;
    const float* row = g_hl + (size_t)n * HCC + h * CCD;
    float v0 = row[lane], v1 = row[lane + 32];
    float s1 = v0 * asrc[h * CCD + lane] + v1 * asrc[h * CCD + lane + 32];
    float s2 = v0 * adst[h * CCD + lane] + v1 * adst[h * CCD + lane + 32];
    #pragma unroll
    for (int off = 16; off; off >>= 1) {
        s1 += __shfl_down_sync(0xFFFFFFFFu, s1, off);
        s2 += __shfl_down_sync(0xFFFFFFFFu, s2, off);
    }
    if (lane == 0) {
        g_as[n * HH + h] = s1;
        g_ad[n * HH + h] = s2;
    }
}

// ---------------- GAT gather: one warp per dst, single pass, unroll x4 ----------------
__global__ void k_gat_gather() {
    int gid = blockIdx.x * blockDim.x + threadIdx.x;
    int dst = gid >> 5;
    int lane = gid & 31;
    if (dst >= NN) return;
    int h = lane >> 3;
    float adh = g_ad[dst * HH + h];
    int beg = g_rowstart[dst], end = g_rowstart[dst + 1];

    float sum = 0.f;
    float acc[8];
    #pragma unroll
    for (int k = 0; k < 8; k++) acc[k] = 0.f;

    int e = beg;
    for (; e + 3 < end; e += 4) {
        int s0 = __ldg(&g_csrsrc[e + 0]);
        int s1 = __ldg(&g_csrsrc[e + 1]);
        int s2 = __ldg(&g_csrsrc[e + 2]);
        int s3 = __ldg(&g_csrsrc[e + 3]);
        float v0 = __ldg(&g_as[s0 * HH + h]) + adh;
        float v1 = __ldg(&g_as[s1 * HH + h]) + adh;
        float v2 = __ldg(&g_as[s2 * HH + h]) + adh;
        float v3 = __ldg(&g_as[s3 * HH + h]) + adh;
        v0 = (v0 > 0.f) ? v0 : 0.2f * v0;
        v1 = (v1 > 0.f) ? v1 : 0.2f * v1;
        v2 = (v2 > 0.f) ? v2 : 0.2f * v2;
        v3 = (v3 > 0.f) ? v3 : 0.2f * v3;
        float w0 = __expf(v0), w1 = __expf(v1), w2 = __expf(v2), w3 = __expf(v3);
        sum += (w0 + w1) + (w2 + w3);
        const float4* hp0 = (const float4*)(g_hl + (size_t)s0 * HCC + lane * 8);
        const float4* hp1 = (const float4*)(g_hl + (size_t)s1 * HCC + lane * 8);
        const float4* hp2 = (const float4*)(g_hl + (size_t)s2 * HCC + lane * 8);
        const float4* hp3 = (const float4*)(g_hl + (size_t)s3 * HCC + lane * 8);
        float4 a0 = __ldg(hp0), b0 = __ldg(hp0 + 1);
        float4 a1 = __ldg(hp1), b1 = __ldg(hp1 + 1);
        float4 a2 = __ldg(hp2), b2 = __ldg(hp2 + 1);
        float4 a3 = __ldg(hp3), b3 = __ldg(hp3 + 1);
        acc[0] += w0 * a0.x + w1 * a1.x + w2 * a2.x + w3 * a3.x;
        acc[1] += w0 * a0.y + w1 * a1.y + w2 * a2.y + w3 * a3.y;
        acc[2] += w0 * a0.z + w1 * a1.z + w2 * a2.z + w3 * a3.z;
        acc[3] += w0 * a0.w + w1 * a1.w + w2 * a2.w + w3 * a3.w;
        acc[4] += w0 * b0.x + w1 * b1.x + w2 * b2.x + w3 * b3.x;
        acc[5] += w0 * b0.y + w1 * b1.y + w2 * b2.y + w3 * b3.y;
        acc[6] += w0 * b0.z + w1 * b1.z + w2 * b2.z + w3 * b3.z;
        acc[7] += w0 * b0.w + w1 * b1.w + w2 * b2.w + w3 * b3.w;
    }
    for (; e < end; e++) {
        int s0 = __ldg(&g_csrsrc[e]);
        float v0 = __ldg(&g_as[s0 * HH + h]) + adh;
        v0 = (v0 > 0.f) ? v0 : 0.2f * v0;
        float w0 = __expf(v0);
        sum += w0;
        const float4* hp0 = (const float4*)(g_hl + (size_t)s0 * HCC + lane * 8);
        float4 a0 = __ldg(hp0), b0 = __ldg(hp0 + 1);
        acc[0] += w0 * a0.x; acc[1] += w0 * a0.y;
        acc[2] += w0 * a0.z; acc[3] += w0 * a0.w;
        acc[4] += w0 * b0.x; acc[5] += w0 * b0.y;
        acc[6] += w0 * b0.z; acc[7] += w0 * b0.w;
    }
    float rs = 1.f / sum;
    float4* op = (float4*)(g_hagg + (size_t)dst * HCC + lane * 8);
    op[0] = make_float4(acc[0] * rs, acc[1] * rs, acc[2] * rs, acc[3] * rs);
    op[1] = make_float4(acc[4] * rs, acc[5] * rs, acc[6] * rs, acc[7] * rs);
}

// ---------------- BatchNorm stats ----------------
__global__ void k_bn_stats() {
    int c = threadIdx.x;
    int r0 = blockIdx.x * 100;
    float s = 0.f, sq = 0.f;
    for (int r = r0; r < r0 + 100; r++) {
        float v = g_hagg[(size_t)r * HCC + c];
        s += v;
        sq += v * v;
    }
    atomicAdd(&g_sum[c], (double)s);
    atomicAdd(&g_sumsq[c], (double)sq);
}

__global__ void k_bn_final() {
    int c = threadIdx.x;
    double m = g_sum[c] / (double)NN;
    double var = g_sumsq[c] / (double)NN - m * m;
    g_mean[c] = (float)m;
    g_rstd[c] = (float)(1.0 / sqrt(var + (double)BNEPS));
    g_sum[c] = 0.0;
    g_sumsq[c] = 0.0;
}

// ---------------- pooling (fused layer-2 BN + ELU) + FC ----------------
__global__ void k_pool(const float* __restrict__ gamma, const float* __restrict__ beta) {
    int b = blockIdx.x >> 2;
    int part = blockIdx.x & 3;
    int c = threadIdx.x;
    float ga = gamma[c], be = beta[c], m = g_mean[c], r_ = g_rstd[c];
    int st = g_starts[b], cnt = g_counts[b];
    int per = (cnt + 3) >> 2;
    int r0 = st + part * per;
    int r1 = st + cnt; if (r0 + per < r1) r1 = r0 + per;
    float s = 0.f;
    for (int r = r0; r < r1; r++) {
        float v = g_hagg[(size_t)r * HCC + c];
        float y = ga * (v - m) * r_ + be;
        s += (y > 0.f) ? y : expm1f(y);
    }
    atomicAdd(&g_pooled[b * HCC + c], s);
}

__global__ void k_fc(const float* __restrict__ Wfc, const float* __restrict__ bfc,
                     float* __restrict__ out) {
    int b = blockIdx.x;
    int j = threadIdx.x;
    float scale = 1.f / (float)g_counts[b];
    float s = 0.f;
    #pragma unroll 4
    for (int k = 0; k < HCC; k++) s += g_pooled[b * HCC + k] * Wfc[k * OUTD + j];
    out[b * OUTD + j] = s * scale + bfc[j];
}

// ---------------- launch ----------------
extern "C" void kernel_launch(void* const* d_in, const int* in_sizes, int n_in,
                              void* d_out, int out_size) {
    const float* x      = (const float*)d_in[0];
    const int*   ei     = (const int*)d_in[1];
    const int*   batch  = (const int*)d_in[2];
    const float* Wpos   = (const float*)d_in[3];
    const float* bpos   = (const float*)d_in[4];
    const float* W1     = (const float*)d_in[5];
    const float* asrc1  = (const float*)d_in[6];
    const float* adst1  = (const float*)d_in[7];
    const float* gamma1 = (const float*)d_in[9];
    const float* beta1  = (const float*)d_in[10];
    const float* W2     = (const float*)d_in[11];
    const float* asrc2  = (const float*)d_in[12];
    const float* adst2  = (const float*)d_in[13];
    const float* gamma2 = (const float*)d_in[15];
    const float* beta2  = (const float*)d_in[16];
    const float* Wfc    = (const float*)d_in[17];
    const float* bfc    = (const float*)d_in[18];
    float* out = (float*)d_out;

    const int NB = (NN + 255) / 256;
    const int EB = (ETOTE + 255) / 256;

    float* g_h0_p;  cudaGetSymbolAddress((void**)&g_h0_p,  g_h0);

    k_prep_zero<<<NB, 256>>>();
    k_count_nodes<<<NB, 256>>>(batch);
    k_graph_meta<<<1, 64>>>();
    k_build_h0<<<(NN * (ENHD / 4) + 255) / 256, 256>>>(x, batch, Wpos, bpos);

    k_edge_count<<<EB, 256>>>(ei);
    k_scanA<<<NB, 256>>>();
    k_scanB<<<1, 256>>>();
    k_scanC<<<NB, 256>>>();
    k_edge_fill<<<EB, 256>>>(ei);

    dim3 ggrid((NN + 127) / 128, 2);

    // layer 1
    k_convW<<<(HCC * 448 + 255) / 256, 256>>>(W1, ENHD, 448);
    k_convA<<<(NN * (ENHD / 4) + 255) / 256, 256>>>(g_h0_p, ENHD, 448);
    k_gemm_mma<448><<<ggrid, 256>>>();
    k_alpha<<<(NN * HH * 32) / 256, 256>>>(asrc1, adst1);
    k_gat_gather<<<(NN * 32) / 256, 256>>>();
    k_bn_stats<<<500, 256>>>();
    k_bn_final<<<1, 256>>>();

    // layer 2 (BN1+ELU fused into convA_bn)
    k_convW<<<(HCC * 768 + 255) / 256, 256>>>(W2, HCC, 768);
    k_convA_bn<<<(NN * 64 + 255) / 256, 256>>>(gamma1, beta1);
    k_gemm_mma<768><<<ggrid, 256>>>();
    k_alpha<<<(NN * HH * 32) / 256, 256>>>(asrc2, adst2);
    k_gat_gather<<<(NN * 32) / 256, 256>>>();
    k_bn_stats<<<500, 256>>>();
    k_bn_final<<<1, 256>>>();

    // pool (BN2+ELU fused) + fc
    k_pool<<<BB * 4, 256>>>(gamma2, beta2);
    k_fc<<<BB, 128>>>(Wfc, bfc, out);
}

// round 12
// speedup vs baseline: 1.0304x; 1.0304x over previous
#include <cuda_runtime.h>
#include <cuda_bf16.h>
#include <cstdint>
#include <math.h>

#define NN    50000
#define EE    800000
#define ETOTE 850000
#define BB    64
#define FIN   128
#define POSD  16
#define ENHD  144
#define HH    4
#define CCD   64
#define HCC   256
#define OUTD  128
#define BNEPS 1e-5f

// ---------------- scratch ----------------
__device__ float  g_h0[NN * ENHD];
__device__ float  g_hl[NN * HCC];
__device__ float  g_hagg[NN * HCC];
__device__ __nv_bfloat16 g_abf[(NN + 256) * 768];
__device__ __nv_bfloat16 g_wbf[256 * 768];
__device__ float  g_as[NN * HH];
__device__ float  g_ad[NN * HH];
__device__ int    g_counts[BB];
__device__ int    g_starts[BB];
__device__ int    g_gridsz[BB];
__device__ float  g_denomv[BB];
__device__ int    g_indeg[NN];
__device__ int    g_rowstart[NN + 1];
__device__ int    g_fillpos[NN];
__device__ int    g_csrsrc[ETOTE];
__device__ int    g_bsum[256];
__device__ double g_sum[HCC];
__device__ double g_sumsq[HCC];
__device__ float  g_mean[HCC];
__device__ float  g_rstd[HCC];
__device__ float  g_pooled[BB * HCC];

// ---------------- graph meta ----------------
__global__ void k_prep_zero() {
    int i = blockIdx.x * blockDim.x + threadIdx.x;
    if (i < NN) g_indeg[i] = 0;
    if (i < BB) g_counts[i] = 0;
    if (i < HCC) { g_sum[i] = 0.0; g_sumsq[i] = 0.0; }
    if (i < BB * HCC) g_pooled[i] = 0.f;
}

__global__ void k_count_nodes(const int* __restrict__ batch) {
    int i = blockIdx.x * blockDim.x + threadIdx.x;
    if (i < NN) atomicAdd(&g_counts[batch[i]], 1);
}

__global__ void k_graph_meta() {
    int b = threadIdx.x;
    if (b >= BB) return;
    int st = 0;
    for (int j = 0; j < b; j++) st += g_counts[j];
    g_starts[b] = st;
    int c = g_counts[b];
    int g = (int)ceil(sqrt((double)c));
    g_gridsz[b] = g;
    int d = g - 1; if (d < 1) d = 1;
    g_denomv[b] = (float)d;
}

__global__ void k_build_h0(const float* __restrict__ x, const int* __restrict__ batch,
                           const float* __restrict__ Wpos, const float* __restrict__ bpos) {
    int tid = blockIdx.x * blockDim.x + threadIdx.x;
    if (tid >= NN * (ENHD / 4)) return;
    int n = tid / (ENHD / 4);
    int f4 = tid - n * (ENHD / 4);
    float4 v;
    if (f4 < FIN / 4) {
        v = ((const float4*)x)[(size_t)n * (FIN / 4) + f4];
    } else {
        int b = batch[n];
        int i = n - g_starts[b];
        int g = g_gridsz[b];
        float denom = g_denomv[b];
        int row = i / g;
        int col = i - row * g;
        float p0 = (float)row / denom;
        float p1 = (float)col / denom;
        int j = (f4 - FIN / 4) * 4;
        v.x = p0 * Wpos[j + 0] + p1 * Wpos[POSD + j + 0] + bpos[j + 0];
        v.y = p0 * Wpos[j + 1] + p1 * Wpos[POSD + j + 1] + bpos[j + 1];
        v.z = p0 * Wpos[j + 2] + p1 * Wpos[POSD + j + 2] + bpos[j + 2];
        v.w = p0 * Wpos[j + 3] + p1 * Wpos[POSD + j + 3] + bpos[j + 3];
    }
    ((float4*)g_h0)[tid] = v;
}

// ---------------- CSR by destination ----------------
__global__ void k_edge_count(const int* __restrict__ ei) {
    int e = blockIdx.x * blockDim.x + threadIdx.x;
    if (e >= ETOTE) return;
    int dst = (e < EE) ? ei[EE + e] : (e - EE);
    atomicAdd(&g_indeg[dst], 1);
}

__global__ void k_scanA() {
    __shared__ int s[256];
    int i = blockIdx.x * 256 + threadIdx.x;
    int v = (i < NN) ? g_indeg[i] : 0;
    s[threadIdx.x] = v;
    __syncthreads();
    for (int off = 1; off < 256; off <<= 1) {
        int t = (threadIdx.x >= off) ? s[threadIdx.x - off] : 0;
        __syncthreads();
        s[threadIdx.x] += t;
        __syncthreads();
    }
    if (i < NN) g_rowstart[i] = s[threadIdx.x] - v;
    if (threadIdx.x == 255) g_bsum[blockIdx.x] = s[255];
}

__global__ void k_scanB() {
    __shared__ int s[256];
    int t = threadIdx.x;
    int v = (t < 196) ? g_bsum[t] : 0;
    s[t] = v;
    __syncthreads();
    for (int off = 1; off < 256; off <<= 1) {
        int u = (t >= off) ? s[t - off] : 0;
        __syncthreads();
        s[t] += u;
        __syncthreads();
    }
    if (t < 196) g_bsum[t] = s[t] - v;
}

__global__ void k_scanC() {
    int i = blockIdx.x * 256 + threadIdx.x;
    if (i < NN) {
        int rs = g_rowstart[i] + g_bsum[blockIdx.x];
        g_rowstart[i] = rs;
        g_fillpos[i] = rs;
    }
    if (i == 0) g_rowstart[NN] = ETOTE;
}

__global__ void k_edge_fill(const int* __restrict__ ei) {
    int e = blockIdx.x * blockDim.x + threadIdx.x;
    if (e >= ETOTE) return;
    int src, dst;
    if (e < EE) { src = ei[e]; dst = ei[EE + e]; }
    else        { src = e - EE; dst = src; }
    int p = atomicAdd(&g_fillpos[dst], 1);
    g_csrsrc[p] = src;
}

// ---------------- bf16x3 split conversion (vectorized) ----------------
__global__ void k_convA(const float* __restrict__ A, int K, int Kp) {
    int idx = blockIdx.x * blockDim.x + threadIdx.x;      // over NN*K/4
    if (idx >= NN * (K / 4)) return;
    int n = idx / (K / 4), k = (idx - n * (K / 4)) * 4;
    float4 x = ((const float4*)A)[idx];
    __nv_bfloat162 h0 = __float22bfloat162_rn(make_float2(x.x, x.y));
    __nv_bfloat162 h1 = __float22bfloat162_rn(make_float2(x.z, x.w));
    float2 hlo0 = __bfloat1622float2(h0), hlo1 = __bfloat1622float2(h1);
    __nv_bfloat162 l0 = __float22bfloat162_rn(make_float2(x.x - hlo0.x, x.y - hlo0.y));
    __nv_bfloat162 l1 = __float22bfloat162_rn(make_float2(x.z - hlo1.x, x.w - hlo1.y));
    size_t base = (size_t)n * Kp + k;
    *(__nv_bfloat162*)(g_abf + base) = h0;
    *(__nv_bfloat162*)(g_abf + base + 2) = h1;
    *(__nv_bfloat162*)(g_abf + base + K) = l0;
    *(__nv_bfloat162*)(g_abf + base + K + 2) = l1;
    *(__nv_bfloat162*)(g_abf + base + 2 * K) = h0;
    *(__nv_bfloat162*)(g_abf + base + 2 * K + 2) = h1;
}

// layer-2 A conversion with fused BatchNorm + ELU
__global__ void k_convA_bn(const float* __restrict__ gamma, const float* __restrict__ beta) {
    int idx = blockIdx.x * blockDim.x + threadIdx.x;      // over NN*64
    if (idx >= NN * 64) return;
    int n = idx >> 6, k = (idx & 63) * 4;
    float4 v = ((const float4*)g_hagg)[idx];
    float y0 = gamma[k + 0] * (v.x - g_mean[k + 0]) * g_rstd[k + 0] + beta[k + 0];
    float y1 = gamma[k + 1] * (v.y - g_mean[k + 1]) * g_rstd[k + 1] + beta[k + 1];
    float y2 = gamma[k + 2] * (v.z - g_mean[k + 2]) * g_rstd[k + 2] + beta[k + 2];
    float y3 = gamma[k + 3] * (v.w - g_mean[k + 3]) * g_rstd[k + 3] + beta[k + 3];
    y0 = (y0 > 0.f) ? y0 : expm1f(y0);
    y1 = (y1 > 0.f) ? y1 : expm1f(y1);
    y2 = (y2 > 0.f) ? y2 : expm1f(y2);
    y3 = (y3 > 0.f) ? y3 : expm1f(y3);
    __nv_bfloat162 h0 = __float22bfloat162_rn(make_float2(y0, y1));
    __nv_bfloat162 h1 = __float22bfloat162_rn(make_float2(y2, y3));
    float2 f0 = __bfloat1622float2(h0), f1 = __bfloat1622float2(h1);
    __nv_bfloat162 l0 = __float22bfloat162_rn(make_float2(y0 - f0.x, y1 - f0.y));
    __nv_bfloat162 l1 = __float22bfloat162_rn(make_float2(y2 - f1.x, y3 - f1.y));
    size_t base = (size_t)n * 768 + k;
    *(__nv_bfloat162*)(g_abf + base) = h0;
    *(__nv_bfloat162*)(g_abf + base + 2) = h1;
    *(__nv_bfloat162*)(g_abf + base + 256) = l0;
    *(__nv_bfloat162*)(g_abf + base + 258) = l1;
    *(__nv_bfloat162*)(g_abf + base + 512) = h0;
    *(__nv_bfloat162*)(g_abf + base + 514) = h1;
}

// W' transposed to [n][k']: [W_hi | W_hi | W_lo], pad zero
__global__ void k_convW(const float* __restrict__ W, int K, int Kp) {
    int idx = blockIdx.x * blockDim.x + threadIdx.x;
    if (idx >= HCC * Kp) return;
    int n = idx / Kp, k = idx - n * Kp;
    __nv_bfloat16 v;
    if (k < K) {
        v = __float2bfloat16(W[(size_t)k * HCC + n]);
    } else if (k < 2 * K) {
        v = __float2bfloat16(W[(size_t)(k - K) * HCC + n]);
    } else if (k < 3 * K) {
        float x = W[(size_t)(k - 2 * K) * HCC + n];
        __nv_bfloat16 hi = __float2bfloat16(x);
        v = __float2bfloat16(x - __bfloat162float(hi));
    } else {
        v = __float2bfloat16(0.f);
    }
    g_wbf[idx] = v;
}

// ---------------- HMMA GEMM: g_hl[M,256] = A'[M,KP] @ W'^T ----------------
template<int KP>
__global__ void __launch_bounds__(256) k_gemm_mma() {
    __shared__ __nv_bfloat16 As[2][128][40];
    __shared__ __nv_bfloat16 Bs[2][128][40];
    const int tid = threadIdx.x;
    const int lane = tid & 31, wid = tid >> 5;
    const int wm = wid & 1, wn = wid >> 1;
    const int g = lane >> 2, tq = lane & 3;
    const int m0 = blockIdx.x * 128, n0 = blockIdx.y * 128;

    float acc[4][4][4];
    #pragma unroll
    for (int a = 0; a < 4; a++)
        #pragma unroll
        for (int b = 0; b < 4; b++)
            #pragma unroll
            for (int c = 0; c < 4; c++) acc[a][b][c] = 0.f;

    const int lr = tid >> 2;
    const int lc = tid & 3;
    const __nv_bfloat16* gA = g_abf + (size_t)m0 * KP;
    const __nv_bfloat16* gB = g_wbf + (size_t)n0 * KP;

    uint4 pa[2], pb[2];
    auto ld_chunk = [&](int k0) {
        #pragma unroll
        for (int i = 0; i < 2; i++) {
            int row = lr + i * 64;
            pa[i] = *(const uint4*)(gA + (size_t)row * KP + k0 + lc * 8);
            pb[i] = *(const uint4*)(gB + (size_t)row * KP + k0 + lc * 8);
        }
    };
    auto st_chunk = [&](int b) {
        #pragma unroll
        for (int i = 0; i < 2; i++) {
            int row = lr + i * 64;
            *(uint4*)&As[b][row][lc * 8] = pa[i];
            *(uint4*)&Bs[b][row][lc * 8] = pb[i];
        }
    };

    ld_chunk(0);
    st_chunk(0);
    __syncthreads();

    const int C = KP / 32;
    for (int c = 0; c < C; c++) {
        int cur = c & 1;
        if (c + 1 < C) ld_chunk((c + 1) * 32);
        #pragma unroll
        for (int ks = 0; ks < 2; ks++) {
            uint32_t af[4][4], bf[4][2];
            #pragma unroll
            for (int mt = 0; mt < 4; mt++) {
                int r = wm * 64 + mt * 16 + g;
                int cbase = ks * 16 + tq * 2;
                af[mt][0] = *(const uint32_t*)&As[cur][r][cbase];
                af[mt][1] = *(const uint32_t*)&As[cur][r + 8][cbase];
                af[mt][2] = *(const uint32_t*)&As[cur][r][cbase + 8];
                af[mt][3] = *(const uint32_t*)&As[cur][r + 8][cbase + 8];
            }
            #pragma unroll
            for (int nt = 0; nt < 4; nt++) {
                int r = wn * 32 + nt * 8 + g;
                int cbase = ks * 16 + tq * 2;
                bf[nt][0] = *(const uint32_t*)&Bs[cur][r][cbase];
                bf[nt][1] = *(const uint32_t*)&Bs[cur][r][cbase + 8];
            }
            #pragma unroll
            for (int mt = 0; mt < 4; mt++)
                #pragma unroll
                for (int nt = 0; nt < 4; nt++)
                    asm volatile(
                        "mma.sync.aligned.m16n8k16.row.col.f32.bf16.bf16.f32 "
                        "{%0,%1,%2,%3}, {%4,%5,%6,%7}, {%8,%9}, {%0,%1,%2,%3};\n"
                        : "+f"(acc[mt][nt][0]), "+f"(acc[mt][nt][1]),
                          "+f"(acc[mt][nt][2]), "+f"(acc[mt][nt][3])
                        : "r"(af[mt][0]), "r"(af[mt][1]), "r"(af[mt][2]), "r"(af[mt][3]),
                          "r"(bf[nt][0]), "r"(bf[nt][1]));
        }
        if (c + 1 < C) st_chunk(1 - cur);
        __syncthreads();
    }

    #pragma unroll
    for (int mt = 0; mt < 4; mt++) {
        int r0 = m0 + wm * 64 + mt * 16 + g;
        #pragma unroll
        for (int nt = 0; nt < 4; nt++) {
            int cc = n0 + wn * 32 + nt * 8 + tq * 2;
            if (r0 < NN)
                *(float2*)&g_hl[(size_t)r0 * HCC + cc] =
                    make_float2(acc[mt][nt][0], acc[mt][nt][1]);
            if (r0 + 8 < NN)
                *(float2*)&g_hl[(size_t)(r0 + 8) * HCC + cc] =
                    make_float2(acc[mt][nt][2], acc[mt][nt][3]);
        }
    }
}

// ---------------- attention logits ----------------
__global__ void k_alpha(const float* __restrict__ asrc, const float* __restrict__ adst) {
    int gid = blockIdx.x * blockDim.x + threadIdx.x;
    int warp = gid >> 5;
    int lane = gid & 31;
    if (warp >= NN * HH) return;
    int n = warp >> 2;
    int h = warp & 3;
    const float* row = g_hl + (size_t)n * HCC + h * CCD;
    float v0 = row[lane], v1 = row[lane + 32];
    float s1 = v0 * asrc[h * CCD + lane] + v1 * asrc[h * CCD + lane + 32];
    float s2 = v0 * adst[h * CCD + lane] + v1 * adst[h * CCD + lane + 32];
    #pragma unroll
    for (int off = 16; off; off >>= 1) {
        s1 += __shfl_down_sync(0xFFFFFFFFu, s1, off);
        s2 += __shfl_down_sync(0xFFFFFFFFu, s2, off);
    }
    if (lane == 0) {
        g_as[n * HH + h] = s1;
        g_ad[n * HH + h] = s2;
    }
}

// ---------------- GAT gather: one warp per dst, single pass, unroll x2 (r6-proven) ----------------
__global__ void k_gat_gather() {
    int gid = blockIdx.x * blockDim.x + threadIdx.x;
    int dst = gid >> 5;
    int lane = gid & 31;
    if (dst >= NN) return;
    int h = lane >> 3;
    float adh = g_ad[dst * HH + h];
    int beg = g_rowstart[dst], end = g_rowstart[dst + 1];

    float sum = 0.f;
    float acc[8];
    #pragma unroll
    for (int k = 0; k < 8; k++) acc[k] = 0.f;

    int e = beg;
    for (; e + 1 < end; e += 2) {
        int s0 = __ldg(&g_csrsrc[e]);
        int s1 = __ldg(&g_csrsrc[e + 1]);
        float v0 = __ldg(&g_as[s0 * HH + h]) + adh;
        float v1 = __ldg(&g_as[s1 * HH + h]) + adh;
        v0 = (v0 > 0.f) ? v0 : 0.2f * v0;
        v1 = (v1 > 0.f) ? v1 : 0.2f * v1;
        float w0 = __expf(v0);
        float w1 = __expf(v1);
        sum += w0 + w1;
        const float4* hp0 = (const float4*)(g_hl + (size_t)s0 * HCC + lane * 8);
        const float4* hp1 = (const float4*)(g_hl + (size_t)s1 * HCC + lane * 8);
        float4 p0a = __ldg(hp0), p0b = __ldg(hp0 + 1);
        float4 p1a = __ldg(hp1), p1b = __ldg(hp1 + 1);
        acc[0] += w0 * p0a.x + w1 * p1a.x;
        acc[1] += w0 * p0a.y + w1 * p1a.y;
        acc[2] += w0 * p0a.z + w1 * p1a.z;
        acc[3] += w0 * p0a.w + w1 * p1a.w;
        acc[4] += w0 * p0b.x + w1 * p1b.x;
        acc[5] += w0 * p0b.y + w1 * p1b.y;
        acc[6] += w0 * p0b.z + w1 * p1b.z;
        acc[7] += w0 * p0b.w + w1 * p1b.w;
    }
    if (e < end) {
        int s0 = __ldg(&g_csrsrc[e]);
        float v0 = __ldg(&g_as[s0 * HH + h]) + adh;
        v0 = (v0 > 0.f) ? v0 : 0.2f * v0;
        float w0 = __expf(v0);
        sum += w0;
        const float4* hp0 = (const float4*)(g_hl + (size_t)s0 * HCC + lane * 8);
        float4 p0a = __ldg(hp0), p0b = __ldg(hp0 + 1);
        acc[0] += w0 * p0a.x; acc[1] += w0 * p0a.y;
        acc[2] += w0 * p0a.z; acc[3] += w0 * p0a.w;
        acc[4] += w0 * p0b.x; acc[5] += w0 * p0b.y;
        acc[6] += w0 * p0b.z; acc[7] += w0 * p0b.w;
    }
    float rs = 1.f / sum;
    float4* op = (float4*)(g_hagg + (size_t)dst * HCC + lane * 8);
    op[0] = make_float4(acc[0] * rs, acc[1] * rs, acc[2] * rs, acc[3] * rs);
    op[1] = make_float4(acc[4] * rs, acc[5] * rs, acc[6] * rs, acc[7] * rs);
}

// ---------------- BatchNorm stats ----------------
__global__ void k_bn_stats() {
    int c = threadIdx.x;
    int r0 = blockIdx.x * 200;
    float s = 0.f, sq = 0.f;
    for (int r = r0; r < r0 + 200; r++) {
        float v = g_hagg[(size_t)r * HCC + c];
        s += v;
        sq += v * v;
    }
    atomicAdd(&g_sum[c], (double)s);
    atomicAdd(&g_sumsq[c], (double)sq);
}

__global__ void k_bn_final() {
    int c = threadIdx.x;
    double m = g_sum[c] / (double)NN;
    double var = g_sumsq[c] / (double)NN - m * m;
    g_mean[c] = (float)m;
    g_rstd[c] = (float)(1.0 / sqrt(var + (double)BNEPS));
    g_sum[c] = 0.0;
    g_sumsq[c] = 0.0;
}

// ---------------- pooling (fused layer-2 BN + ELU) + FC ----------------
__global__ void k_pool(const float* __restrict__ gamma, const float* __restrict__ beta) {
    int b = blockIdx.x >> 2;
    int part = blockIdx.x & 3;
    int c = threadIdx.x;
    float ga = gamma[c], be = beta[c], m = g_mean[c], r_ = g_rstd[c];
    int st = g_starts[b], cnt = g_counts[b];
    int per = (cnt + 3) >> 2;
    int r0 = st + part * per;
    int r1 = st + cnt; if (r0 + per < r1) r1 = r0 + per;
    float s = 0.f;
    for (int r = r0; r < r1; r++) {
        float v = g_hagg[(size_t)r * HCC + c];
        float y = ga * (v - m) * r_ + be;
        s += (y > 0.f) ? y : expm1f(y);
    }
    atomicAdd(&g_pooled[b * HCC + c], s);
}

__global__ void k_fc(const float* __restrict__ Wfc, const float* __restrict__ bfc,
                     float* __restrict__ out) {
    int b = blockIdx.x;
    int j = threadIdx.x;
    float scale = 1.f / (float)g_counts[b];
    float s = 0.f;
    #pragma unroll 4
    for (int k = 0; k < HCC; k++) s += g_pooled[b * HCC + k] * Wfc[k * OUTD + j];
    out[b * OUTD + j] = s * scale + bfc[j];
}

// ---------------- launch ----------------
extern "C" void kernel_launch(void* const* d_in, const int* in_sizes, int n_in,
                              void* d_out, int out_size) {
    const float* x      = (const float*)d_in[0];
    const int*   ei     = (const int*)d_in[1];
    const int*   batch  = (const int*)d_in[2];
    const float* Wpos   = (const float*)d_in[3];
    const float* bpos   = (const float*)d_in[4];
    const float* W1     = (const float*)d_in[5];
    const float* asrc1  = (const float*)d_in[6];
    const float* adst1  = (const float*)d_in[7];
    const float* gamma1 = (const float*)d_in[9];
    const float* beta1  = (const float*)d_in[10];
    const float* W2     = (const float*)d_in[11];
    const float* asrc2  = (const float*)d_in[12];
    const float* adst2  = (const float*)d_in[13];
    const float* gamma2 = (const float*)d_in[15];
    const float* beta2  = (const float*)d_in[16];
    const float* Wfc    = (const float*)d_in[17];
    const float* bfc    = (const float*)d_in[18];
    float* out = (float*)d_out;

    const int NB = (NN + 255) / 256;
    const int EB = (ETOTE + 255) / 256;

    float* g_h0_p;  cudaGetSymbolAddress((void**)&g_h0_p,  g_h0);

    k_prep_zero<<<NB, 256>>>();
    k_count_nodes<<<NB, 256>>>(batch);
    k_graph_meta<<<1, 64>>>();
    k_build_h0<<<(NN * (ENHD / 4) + 255) / 256, 256>>>(x, batch, Wpos, bpos);

    k_edge_count<<<EB, 256>>>(ei);
    k_scanA<<<NB, 256>>>();
    k_scanB<<<1, 256>>>();
    k_scanC<<<NB, 256>>>();
    k_edge_fill<<<EB, 256>>>(ei);

    dim3 ggrid((NN + 127) / 128, 2);

    // layer 1
    k_convW<<<(HCC * 448 + 255) / 256, 256>>>(W1, ENHD, 448);
    k_convA<<<(NN * (ENHD / 4) + 255) / 256, 256>>>(g_h0_p, ENHD, 448);
    k_gemm_mma<448><<<ggrid, 256>>>();
    k_alpha<<<(NN * HH * 32) / 256, 256>>>(asrc1, adst1);
    k_gat_gather<<<(NN * 32) / 256, 256>>>();
    k_bn_stats<<<250, 256>>>();
    k_bn_final<<<1, 256>>>();

    // layer 2 (BN1+ELU fused into convA_bn)
    k_convW<<<(HCC * 768 + 255) / 256, 256>>>(W2, HCC, 768);
    k_convA_bn<<<(NN * 64 + 255) / 256, 256>>>(gamma1, beta1);
    k_gemm_mma<768><<<ggrid, 256>>>();
    k_alpha<<<(NN * HH * 32) / 256, 256>>>(asrc2, adst2);
    k_gat_gather<<<(NN * 32) / 256, 256>>>();
    k_bn_stats<<<250, 256>>>();
    k_bn_final<<<1, 256>>>();

    // pool (BN2+ELU fused) + fc
    k_pool<<<BB * 4, 256>>>(gamma2, beta2);
    k_fc<<<BB, 128>>>(Wfc, bfc, out);
}

// round 13
// speedup vs baseline: 1.0624x; 1.0310x over previous
#include <cuda_runtime.h>
#include <cuda_bf16.h>
#include <cstdint>
#include <math.h>

#define NN    50000
#define EE    800000
#define ETOTE 850000
#define BB    64
#define FIN   128
#define POSD  16
#define ENHD  144
#define HH    4
#define CCD   64
#define HCC   256
#define OUTD  128
#define BNEPS 1e-5f

// ---------------- scratch ----------------
__device__ float  g_h0[NN * ENHD];
__device__ float  g_hl[NN * HCC];
__device__ __nv_bfloat16 g_hlb[NN * HCC];           // bf16 copy of g_hl for gather messages
__device__ float  g_hagg[NN * HCC];
__device__ __nv_bfloat16 g_abf[(NN + 256) * 768];
__device__ __nv_bfloat16 g_wbf[256 * 768];
__device__ float  g_as[NN * HH];
__device__ float  g_ad[NN * HH];
__device__ int    g_counts[BB];
__device__ int    g_starts[BB];
__device__ int    g_gridsz[BB];
__device__ float  g_denomv[BB];
__device__ int    g_indeg[NN];
__device__ int    g_rowstart[NN + 1];
__device__ int    g_fillpos[NN];
__device__ int    g_csrsrc[ETOTE];
__device__ int    g_bsum[256];
__device__ double g_sum[HCC];
__device__ double g_sumsq[HCC];
__device__ float  g_mean[HCC];
__device__ float  g_rstd[HCC];
__device__ float  g_pooled[BB * HCC];

// ---------------- graph meta ----------------
__global__ void k_prep_zero() {
    int i = blockIdx.x * blockDim.x + threadIdx.x;
    if (i < NN) g_indeg[i] = 0;
    if (i < BB) g_counts[i] = 0;
    if (i < HCC) { g_sum[i] = 0.0; g_sumsq[i] = 0.0; }
    if (i < BB * HCC) g_pooled[i] = 0.f;
}

__global__ void k_count_nodes(const int* __restrict__ batch) {
    int i = blockIdx.x * blockDim.x + threadIdx.x;
    if (i < NN) atomicAdd(&g_counts[batch[i]], 1);
}

__global__ void k_graph_meta() {
    int b = threadIdx.x;
    if (b >= BB) return;
    int st = 0;
    for (int j = 0; j < b; j++) st += g_counts[j];
    g_starts[b] = st;
    int c = g_counts[b];
    int g = (int)ceil(sqrt((double)c));
    g_gridsz[b] = g;
    int d = g - 1; if (d < 1) d = 1;
    g_denomv[b] = (float)d;
}

__global__ void k_build_h0(const float* __restrict__ x, const int* __restrict__ batch,
                           const float* __restrict__ Wpos, const float* __restrict__ bpos) {
    int tid = blockIdx.x * blockDim.x + threadIdx.x;
    if (tid >= NN * (ENHD / 4)) return;
    int n = tid / (ENHD / 4);
    int f4 = tid - n * (ENHD / 4);
    float4 v;
    if (f4 < FIN / 4) {
        v = ((const float4*)x)[(size_t)n * (FIN / 4) + f4];
    } else {
        int b = batch[n];
        int i = n - g_starts[b];
        int g = g_gridsz[b];
        float denom = g_denomv[b];
        int row = i / g;
        int col = i - row * g;
        float p0 = (float)row / denom;
        float p1 = (float)col / denom;
        int j = (f4 - FIN / 4) * 4;
        v.x = p0 * Wpos[j + 0] + p1 * Wpos[POSD + j + 0] + bpos[j + 0];
        v.y = p0 * Wpos[j + 1] + p1 * Wpos[POSD + j + 1] + bpos[j + 1];
        v.z = p0 * Wpos[j + 2] + p1 * Wpos[POSD + j + 2] + bpos[j + 2];
        v.w = p0 * Wpos[j + 3] + p1 * Wpos[POSD + j + 3] + bpos[j + 3];
    }
    ((float4*)g_h0)[tid] = v;
}

// ---------------- CSR by destination ----------------
__global__ void k_edge_count(const int* __restrict__ ei) {
    int e = blockIdx.x * blockDim.x + threadIdx.x;
    if (e >= ETOTE) return;
    int dst = (e < EE) ? ei[EE + e] : (e - EE);
    atomicAdd(&g_indeg[dst], 1);
}

__global__ void k_scanA() {
    __shared__ int s[256];
    int i = blockIdx.x * 256 + threadIdx.x;
    int v = (i < NN) ? g_indeg[i] : 0;
    s[threadIdx.x] = v;
    __syncthreads();
    for (int off = 1; off < 256; off <<= 1) {
        int t = (threadIdx.x >= off) ? s[threadIdx.x - off] : 0;
        __syncthreads();
        s[threadIdx.x] += t;
        __syncthreads();
    }
    if (i < NN) g_rowstart[i] = s[threadIdx.x] - v;
    if (threadIdx.x == 255) g_bsum[blockIdx.x] = s[255];
}

__global__ void k_scanB() {
    __shared__ int s[256];
    int t = threadIdx.x;
    int v = (t < 196) ? g_bsum[t] : 0;
    s[t] = v;
    __syncthreads();
    for (int off = 1; off < 256; off <<= 1) {
        int u = (t >= off) ? s[t - off] : 0;
        __syncthreads();
        s[t] += u;
        __syncthreads();
    }
    if (t < 196) g_bsum[t] = s[t] - v;
}

__global__ void k_scanC() {
    int i = blockIdx.x * 256 + threadIdx.x;
    if (i < NN) {
        int rs = g_rowstart[i] + g_bsum[blockIdx.x];
        g_rowstart[i] = rs;
        g_fillpos[i] = rs;
    }
    if (i == 0) g_rowstart[NN] = ETOTE;
}

__global__ void k_edge_fill(const int* __restrict__ ei) {
    int e = blockIdx.x * blockDim.x + threadIdx.x;
    if (e >= ETOTE) return;
    int src, dst;
    if (e < EE) { src = ei[e]; dst = ei[EE + e]; }
    else        { src = e - EE; dst = src; }
    int p = atomicAdd(&g_fillpos[dst], 1);
    g_csrsrc[p] = src;
}

// ---------------- bf16x3 split conversion (vectorized) ----------------
__global__ void k_convA(const float* __restrict__ A, int K, int Kp) {
    int idx = blockIdx.x * blockDim.x + threadIdx.x;      // over NN*K/4
    if (idx >= NN * (K / 4)) return;
    int n = idx / (K / 4), k = (idx - n * (K / 4)) * 4;
    float4 x = ((const float4*)A)[idx];
    __nv_bfloat162 h0 = __float22bfloat162_rn(make_float2(x.x, x.y));
    __nv_bfloat162 h1 = __float22bfloat162_rn(make_float2(x.z, x.w));
    float2 hlo0 = __bfloat1622float2(h0), hlo1 = __bfloat1622float2(h1);
    __nv_bfloat162 l0 = __float22bfloat162_rn(make_float2(x.x - hlo0.x, x.y - hlo0.y));
    __nv_bfloat162 l1 = __float22bfloat162_rn(make_float2(x.z - hlo1.x, x.w - hlo1.y));
    size_t base = (size_t)n * Kp + k;
    *(__nv_bfloat162*)(g_abf + base) = h0;
    *(__nv_bfloat162*)(g_abf + base + 2) = h1;
    *(__nv_bfloat162*)(g_abf + base + K) = l0;
    *(__nv_bfloat162*)(g_abf + base + K + 2) = l1;
    *(__nv_bfloat162*)(g_abf + base + 2 * K) = h0;
    *(__nv_bfloat162*)(g_abf + base + 2 * K + 2) = h1;
}

// layer-2 A conversion with fused BatchNorm + ELU
__global__ void k_convA_bn(const float* __restrict__ gamma, const float* __restrict__ beta) {
    int idx = blockIdx.x * blockDim.x + threadIdx.x;      // over NN*64
    if (idx >= NN * 64) return;
    int n = idx >> 6, k = (idx & 63) * 4;
    float4 v = ((const float4*)g_hagg)[idx];
    float y0 = gamma[k + 0] * (v.x - g_mean[k + 0]) * g_rstd[k + 0] + beta[k + 0];
    float y1 = gamma[k + 1] * (v.y - g_mean[k + 1]) * g_rstd[k + 1] + beta[k + 1];
    float y2 = gamma[k + 2] * (v.z - g_mean[k + 2]) * g_rstd[k + 2] + beta[k + 2];
    float y3 = gamma[k + 3] * (v.w - g_mean[k + 3]) * g_rstd[k + 3] + beta[k + 3];
    y0 = (y0 > 0.f) ? y0 : expm1f(y0);
    y1 = (y1 > 0.f) ? y1 : expm1f(y1);
    y2 = (y2 > 0.f) ? y2 : expm1f(y2);
    y3 = (y3 > 0.f) ? y3 : expm1f(y3);
    __nv_bfloat162 h0 = __float22bfloat162_rn(make_float2(y0, y1));
    __nv_bfloat162 h1 = __float22bfloat162_rn(make_float2(y2, y3));
    float2 f0 = __bfloat1622float2(h0), f1 = __bfloat1622float2(h1);
    __nv_bfloat162 l0 = __float22bfloat162_rn(make_float2(y0 - f0.x, y1 - f0.y));
    __nv_bfloat162 l1 = __float22bfloat162_rn(make_float2(y2 - f1.x, y3 - f1.y));
    size_t base = (size_t)n * 768 + k;
    *(__nv_bfloat162*)(g_abf + base) = h0;
    *(__nv_bfloat162*)(g_abf + base + 2) = h1;
    *(__nv_bfloat162*)(g_abf + base + 256) = l0;
    *(__nv_bfloat162*)(g_abf + base + 258) = l1;
    *(__nv_bfloat162*)(g_abf + base + 512) = h0;
    *(__nv_bfloat162*)(g_abf + base + 514) = h1;
}

// W' transposed to [n][k']: [W_hi | W_hi | W_lo], pad zero
__global__ void k_convW(const float* __restrict__ W, int K, int Kp) {
    int idx = blockIdx.x * blockDim.x + threadIdx.x;
    if (idx >= HCC * Kp) return;
    int n = idx / Kp, k = idx - n * Kp;
    __nv_bfloat16 v;
    if (k < K) {
        v = __float2bfloat16(W[(size_t)k * HCC + n]);
    } else if (k < 2 * K) {
        v = __float2bfloat16(W[(size_t)(k - K) * HCC + n]);
    } else if (k < 3 * K) {
        float x = W[(size_t)(k - 2 * K) * HCC + n];
        __nv_bfloat16 hi = __float2bfloat16(x);
        v = __float2bfloat16(x - __bfloat162float(hi));
    } else {
        v = __float2bfloat16(0.f);
    }
    g_wbf[idx] = v;
}

// ---------------- HMMA GEMM: g_hl[M,256] = A'[M,KP] @ W'^T ; also writes bf16 copy ----------------
template<int KP>
__global__ void __launch_bounds__(256) k_gemm_mma() {
    __shared__ __nv_bfloat16 As[2][128][40];
    __shared__ __nv_bfloat16 Bs[2][128][40];
    const int tid = threadIdx.x;
    const int lane = tid & 31, wid = tid >> 5;
    const int wm = wid & 1, wn = wid >> 1;
    const int g = lane >> 2, tq = lane & 3;
    const int m0 = blockIdx.x * 128, n0 = blockIdx.y * 128;

    float acc[4][4][4];
    #pragma unroll
    for (int a = 0; a < 4; a++)
        #pragma unroll
        for (int b = 0; b < 4; b++)
            #pragma unroll
            for (int c = 0; c < 4; c++) acc[a][b][c] = 0.f;

    const int lr = tid >> 2;
    const int lc = tid & 3;
    const __nv_bfloat16* gA = g_abf + (size_t)m0 * KP;
    const __nv_bfloat16* gB = g_wbf + (size_t)n0 * KP;

    uint4 pa[2], pb[2];
    auto ld_chunk = [&](int k0) {
        #pragma unroll
        for (int i = 0; i < 2; i++) {
            int row = lr + i * 64;
            pa[i] = *(const uint4*)(gA + (size_t)row * KP + k0 + lc * 8);
            pb[i] = *(const uint4*)(gB + (size_t)row * KP + k0 + lc * 8);
        }
    };
    auto st_chunk = [&](int b) {
        #pragma unroll
        for (int i = 0; i < 2; i++) {
            int row = lr + i * 64;
            *(uint4*)&As[b][row][lc * 8] = pa[i];
            *(uint4*)&Bs[b][row][lc * 8] = pb[i];
        }
    };

    ld_chunk(0);
    st_chunk(0);
    __syncthreads();

    const int C = KP / 32;
    for (int c = 0; c < C; c++) {
        int cur = c & 1;
        if (c + 1 < C) ld_chunk((c + 1) * 32);
        #pragma unroll
        for (int ks = 0; ks < 2; ks++) {
            uint32_t af[4][4], bf[4][2];
            #pragma unroll
            for (int mt = 0; mt < 4; mt++) {
                int r = wm * 64 + mt * 16 + g;
                int cbase = ks * 16 + tq * 2;
                af[mt][0] = *(const uint32_t*)&As[cur][r][cbase];
                af[mt][1] = *(const uint32_t*)&As[cur][r + 8][cbase];
                af[mt][2] = *(const uint32_t*)&As[cur][r][cbase + 8];
                af[mt][3] = *(const uint32_t*)&As[cur][r + 8][cbase + 8];
            }
            #pragma unroll
            for (int nt = 0; nt < 4; nt++) {
                int r = wn * 32 + nt * 8 + g;
                int cbase = ks * 16 + tq * 2;
                bf[nt][0] = *(const uint32_t*)&Bs[cur][r][cbase];
                bf[nt][1] = *(const uint32_t*)&Bs[cur][r][cbase + 8];
            }
            #pragma unroll
            for (int mt = 0; mt < 4; mt++)
                #pragma unroll
                for (int nt = 0; nt < 4; nt++)
                    asm volatile(
                        "mma.sync.aligned.m16n8k16.row.col.f32.bf16.bf16.f32 "
                        "{%0,%1,%2,%3}, {%4,%5,%6,%7}, {%8,%9}, {%0,%1,%2,%3};\n"
                        : "+f"(acc[mt][nt][0]), "+f"(acc[mt][nt][1]),
                          "+f"(acc[mt][nt][2]), "+f"(acc[mt][nt][3])
                        : "r"(af[mt][0]), "r"(af[mt][1]), "r"(af[mt][2]), "r"(af[mt][3]),
                          "r"(bf[nt][0]), "r"(bf[nt][1]));
        }
        if (c + 1 < C) st_chunk(1 - cur);
        __syncthreads();
    }

    #pragma unroll
    for (int mt = 0; mt < 4; mt++) {
        int r0 = m0 + wm * 64 + mt * 16 + g;
        #pragma unroll
        for (int nt = 0; nt < 4; nt++) {
            int cc = n0 + wn * 32 + nt * 8 + tq * 2;
            if (r0 < NN) {
                *(float2*)&g_hl[(size_t)r0 * HCC + cc] =
                    make_float2(acc[mt][nt][0], acc[mt][nt][1]);
                *(__nv_bfloat162*)&g_hlb[(size_t)r0 * HCC + cc] =
                    __float22bfloat162_rn(make_float2(acc[mt][nt][0], acc[mt][nt][1]));
            }
            if (r0 + 8 < NN) {
                *(float2*)&g_hl[(size_t)(r0 + 8) * HCC + cc] =
                    make_float2(acc[mt][nt][2], acc[mt][nt][3]);
                *(__nv_bfloat162*)&g_hlb[(size_t)(r0 + 8) * HCC + cc] =
                    __float22bfloat162_rn(make_float2(acc[mt][nt][2], acc[mt][nt][3]));
            }
        }
    }
}

// ---------------- attention logits (fp32 inputs) ----------------
__global__ void k_alpha(const float* __restrict__ asrc, const float* __restrict__ adst) {
    int gid = blockIdx.x * blockDim.x + threadIdx.x;
    int warp = gid >> 5;
    int lane = gid & 31;
    if (warp >= NN * HH) return;
    int n = warp >> 2;
    int h = warp & 3;
    const float* row = g_hl + (size_t)n * HCC + h * CCD;
    float v0 = row[lane], v1 = row[lane + 32];
    float s1 = v0 * asrc[h * CCD + lane] + v1 * asrc[h * CCD + lane + 32];
    float s2 = v0 * adst[h * CCD + lane] + v1 * adst[h * CCD + lane + 32];
    #pragma unroll
    for (int off = 16; off; off >>= 1) {
        s1 += __shfl_down_sync(0xFFFFFFFFu, s1, off);
        s2 += __shfl_down_sync(0xFFFFFFFFu, s2, off);
    }
    if (lane == 0) {
        g_as[n * HH + h] = s1;
        g_ad[n * HH + h] = s2;
    }
}

// ---------------- GAT gather: one warp per dst, bf16 messages (16B/edge-lane) ----------------
__global__ void k_gat_gather() {
    int gid = blockIdx.x * blockDim.x + threadIdx.x;
    int dst = gid >> 5;
    int lane = gid & 31;
    if (dst >= NN) return;
    int h = lane >> 3;
    float adh = g_ad[dst * HH + h];
    int beg = g_rowstart[dst], end = g_rowstart[dst + 1];

    float sum = 0.f;
    float acc[8];
    #pragma unroll
    for (int k = 0; k < 8; k++) acc[k] = 0.f;

    int e = beg;
    for (; e + 1 < end; e += 2) {
        int s0 = __ldg(&g_csrsrc[e]);
        int s1 = __ldg(&g_csrsrc[e + 1]);
        float v0 = __ldg(&g_as[s0 * HH + h]) + adh;
        float v1 = __ldg(&g_as[s1 * HH + h]) + adh;
        v0 = (v0 > 0.f) ? v0 : 0.2f * v0;
        v1 = (v1 > 0.f) ? v1 : 0.2f * v1;
        float w0 = __expf(v0);
        float w1 = __expf(v1);
        sum += w0 + w1;
        uint4 q0 = __ldg((const uint4*)(g_hlb + (size_t)s0 * HCC + lane * 8));
        uint4 q1 = __ldg((const uint4*)(g_hlb + (size_t)s1 * HCC + lane * 8));
        float2 a0 = __bfloat1622float2(*(__nv_bfloat162*)&q0.x);
        float2 a1 = __bfloat1622float2(*(__nv_bfloat162*)&q0.y);
        float2 a2 = __bfloat1622float2(*(__nv_bfloat162*)&q0.z);
        float2 a3 = __bfloat1622float2(*(__nv_bfloat162*)&q0.w);
        float2 b0 = __bfloat1622float2(*(__nv_bfloat162*)&q1.x);
        float2 b1 = __bfloat1622float2(*(__nv_bfloat162*)&q1.y);
        float2 b2 = __bfloat1622float2(*(__nv_bfloat162*)&q1.z);
        float2 b3 = __bfloat1622float2(*(__nv_bfloat162*)&q1.w);
        acc[0] += w0 * a0.x + w1 * b0.x;
        acc[1] += w0 * a0.y + w1 * b0.y;
        acc[2] += w0 * a1.x + w1 * b1.x;
        acc[3] += w0 * a1.y + w1 * b1.y;
        acc[4] += w0 * a2.x + w1 * b2.x;
        acc[5] += w0 * a2.y + w1 * b2.y;
        acc[6] += w0 * a3.x + w1 * b3.x;
        acc[7] += w0 * a3.y + w1 * b3.y;
    }
    if (e < end) {
        int s0 = __ldg(&g_csrsrc[e]);
        float v0 = __ldg(&g_as[s0 * HH + h]) + adh;
        v0 = (v0 > 0.f) ? v0 : 0.2f * v0;
        float w0 = __expf(v0);
        sum += w0;
        uint4 q0 = __ldg((const uint4*)(g_hlb + (size_t)s0 * HCC + lane * 8));
        float2 a0 = __bfloat1622float2(*(__nv_bfloat162*)&q0.x);
        float2 a1 = __bfloat1622float2(*(__nv_bfloat162*)&q0.y);
        float2 a2 = __bfloat1622float2(*(__nv_bfloat162*)&q0.z);
        float2 a3 = __bfloat1622float2(*(__nv_bfloat162*)&q0.w);
        acc[0] += w0 * a0.x; acc[1] += w0 * a0.y;
        acc[2] += w0 * a1.x; acc[3] += w0 * a1.y;
        acc[4] += w0 * a2.x; acc[5] += w0 * a2.y;
        acc[6] += w0 * a3.x; acc[7] += w0 * a3.y;
    }
    float rs = 1.f / sum;
    float4* op = (float4*)(g_hagg + (size_t)dst * HCC + lane * 8);
    op[0] = make_float4(acc[0] * rs, acc[1] * rs, acc[2] * rs, acc[3] * rs);
    op[1] = make_float4(acc[4] * rs, acc[5] * rs, acc[6] * rs, acc[7] * rs);
}

// ---------------- BatchNorm stats ----------------
__global__ void k_bn_stats() {
    int c = threadIdx.x;
    int r0 = blockIdx.x * 200;
    float s = 0.f, sq = 0.f;
    for (int r = r0; r < r0 + 200; r++) {
        float v = g_hagg[(size_t)r * HCC + c];
        s += v;
        sq += v * v;
    }
    atomicAdd(&g_sum[c], (double)s);
    atomicAdd(&g_sumsq[c], (double)sq);
}

__global__ void k_bn_final() {
    int c = threadIdx.x;
    double m = g_sum[c] / (double)NN;
    double var = g_sumsq[c] / (double)NN - m * m;
    g_mean[c] = (float)m;
    g_rstd[c] = (float)(1.0 / sqrt(var + (double)BNEPS));
    g_sum[c] = 0.0;
    g_sumsq[c] = 0.0;
}

// ---------------- pooling (fused layer-2 BN + ELU) + FC ----------------
__global__ void k_pool(const float* __restrict__ gamma, const float* __restrict__ beta) {
    int b = blockIdx.x >> 2;
    int part = blockIdx.x & 3;
    int c = threadIdx.x;
    float ga = gamma[c], be = beta[c], m = g_mean[c], r_ = g_rstd[c];
    int st = g_starts[b], cnt = g_counts[b];
    int per = (cnt + 3) >> 2;
    int r0 = st + part * per;
    int r1 = st + cnt; if (r0 + per < r1) r1 = r0 + per;
    float s = 0.f;
    for (int r = r0; r < r1; r++) {
        float v = g_hagg[(size_t)r * HCC + c];
        float y = ga * (v - m) * r_ + be;
        s += (y > 0.f) ? y : expm1f(y);
    }
    atomicAdd(&g_pooled[b * HCC + c], s);
}

__global__ void k_fc(const float* __restrict__ Wfc, const float* __restrict__ bfc,
                     float* __restrict__ out) {
    int b = blockIdx.x;
    int j = threadIdx.x;
    float scale = 1.f / (float)g_counts[b];
    float s = 0.f;
    #pragma unroll 4
    for (int k = 0; k < HCC; k++) s += g_pooled[b * HCC + k] * Wfc[k * OUTD + j];
    out[b * OUTD + j] = s * scale + bfc[j];
}

// ---------------- launch ----------------
extern "C" void kernel_launch(void* const* d_in, const int* in_sizes, int n_in,
                              void* d_out, int out_size) {
    const float* x      = (const float*)d_in[0];
    const int*   ei     = (const int*)d_in[1];
    const int*   batch  = (const int*)d_in[2];
    const float* Wpos   = (const float*)d_in[3];
    const float* bpos   = (const float*)d_in[4];
    const float* W1     = (const float*)d_in[5];
    const float* asrc1  = (const float*)d_in[6];
    const float* adst1  = (const float*)d_in[7];
    const float* gamma1 = (const float*)d_in[9];
    const float* beta1  = (const float*)d_in[10];
    const float* W2     = (const float*)d_in[11];
    const float* asrc2  = (const float*)d_in[12];
    const float* adst2  = (const float*)d_in[13];
    const float* gamma2 = (const float*)d_in[15];
    const float* beta2  = (const float*)d_in[16];
    const float* Wfc    = (const float*)d_in[17];
    const float* bfc    = (const float*)d_in[18];
    float* out = (float*)d_out;

    const int NB = (NN + 255) / 256;
    const int EB = (ETOTE + 255) / 256;

    float* g_h0_p;  cudaGetSymbolAddress((void**)&g_h0_p,  g_h0);

    k_prep_zero<<<NB, 256>>>();
    k_count_nodes<<<NB, 256>>>(batch);
    k_graph_meta<<<1, 64>>>();
    k_build_h0<<<(NN * (ENHD / 4) + 255) / 256, 256>>>(x, batch, Wpos, bpos);

    k_edge_count<<<EB, 256>>>(ei);
    k_scanA<<<NB, 256>>>();
    k_scanB<<<1, 256>>>();
    k_scanC<<<NB, 256>>>();
    k_edge_fill<<<EB, 256>>>(ei);

    dim3 ggrid((NN + 127) / 128, 2);

    // layer 1
    k_convW<<<(HCC * 448 + 255) / 256, 256>>>(W1, ENHD, 448);
    k_convA<<<(NN * (ENHD / 4) + 255) / 256, 256>>>(g_h0_p, ENHD, 448);
    k_gemm_mma<448><<<ggrid, 256>>>();
    k_alpha<<<(NN * HH * 32) / 256, 256>>>(asrc1, adst1);
    k_gat_gather<<<(NN * 32) / 256, 256>>>();
    k_bn_stats<<<250, 256>>>();
    k_bn_final<<<1, 256>>>();

    // layer 2 (BN1+ELU fused into convA_bn)
    k_convW<<<(HCC * 768 + 255) / 256, 256>>>(W2, HCC, 768);
    k_convA_bn<<<(NN * 64 + 255) / 256, 256>>>(gamma1, beta1);
    k_gemm_mma<768><<<ggrid, 256>>>();
    k_alpha<<<(NN * HH * 32) / 256, 256>>>(asrc2, adst2);
    k_gat_gather<<<(NN * 32) / 256, 256>>>();
    k_bn_stats<<<250, 256>>>();
    k_bn_final<<<1, 256>>>();

    // pool (BN2+ELU fused) + fc
    k_pool<<<BB * 4, 256>>>(gamma2, beta2);
    k_fc<<<BB, 128>>>(Wfc, bfc, out);
}

// round 16
// speedup vs baseline: 1.6818x; 1.5830x over previous
#include <cuda_runtime.h>
#include <cuda_bf16.h>
#include <cstdint>
#include <math.h>

#define NN    50000
#define EE    800000
#define ETOTE 850000
#define BB    64
#define FIN   128
#define POSD  16
#define ENHD  144
#define HH    4
#define CCD   64
#define HCC   256
#define OUTD  128
#define BNEPS 1e-5f

// ---------------- scratch ----------------
__device__ float  g_h0[NN * ENHD];
__device__ __nv_bfloat16 g_hlb[NN * HCC];           // bf16 feature matrix (gather messages)
__device__ float  g_hagg[NN * HCC];
__device__ __nv_bfloat16 g_abf[(NN + 256) * 768];
__device__ __nv_bfloat16 g_wbf[256 * 768];
__device__ float  g_as[NN * HH];
__device__ float  g_ad[NN * HH];
__device__ int    g_counts[BB];
__device__ int    g_starts[BB];
__device__ int    g_gridsz[BB];
__device__ float  g_denomv[BB];
__device__ int    g_indeg[NN];
__device__ int    g_rowstart[NN + 1];
__device__ int    g_fillpos[NN];
__device__ int    g_csrsrc[ETOTE];
__device__ int    g_bsum[256];
__device__ double g_sum[HCC];
__device__ double g_sumsq[HCC];
__device__ float  g_mean[HCC];
__device__ float  g_rstd[HCC];
__device__ float  g_pooled[BB * HCC];

// ---------------- graph meta ----------------
__global__ void k_prep_zero() {
    int i = blockIdx.x * blockDim.x + threadIdx.x;
    if (i < NN) {
        g_indeg[i] = 0;
        float4 z = make_float4(0.f, 0.f, 0.f, 0.f);
        ((float4*)g_as)[i] = z;     // zero alpha accumulators (layer 1)
        ((float4*)g_ad)[i] = z;
    }
    if (i < BB) g_counts[i] = 0;
    if (i < HCC) { g_sum[i] = 0.0; g_sumsq[i] = 0.0; }
    if (i < BB * HCC) g_pooled[i] = 0.f;
}

__global__ void k_count_nodes(const int* __restrict__ batch) {
    int i = blockIdx.x * blockDim.x + threadIdx.x;
    if (i < NN) atomicAdd(&g_counts[batch[i]], 1);
}

__global__ void k_graph_meta() {
    int b = threadIdx.x;
    if (b >= BB) return;
    int st = 0;
    for (int j = 0; j < b; j++) st += g_counts[j];
    g_starts[b] = st;
    int c = g_counts[b];
    int g = (int)ceil(sqrt((double)c));
    g_gridsz[b] = g;
    int d = g - 1; if (d < 1) d = 1;
    g_denomv[b] = (float)d;
}

__global__ void k_build_h0(const float* __restrict__ x, const int* __restrict__ batch,
                           const float* __restrict__ Wpos, const float* __restrict__ bpos) {
    int tid = blockIdx.x * blockDim.x + threadIdx.x;
    if (tid >= NN * (ENHD / 4)) return;
    int n = tid / (ENHD / 4);
    int f4 = tid - n * (ENHD / 4);
    float4 v;
    if (f4 < FIN / 4) {
        v = ((const float4*)x)[(size_t)n * (FIN / 4) + f4];
    } else {
        int b = batch[n];
        int i = n - g_starts[b];
        int g = g_gridsz[b];
        float denom = g_denomv[b];
        int row = i / g;
        int col = i - row * g;
        float p0 = (float)row / denom;
        float p1 = (float)col / denom;
        int j = (f4 - FIN / 4) * 4;
        v.x = p0 * Wpos[j + 0] + p1 * Wpos[POSD + j + 0] + bpos[j + 0];
        v.y = p0 * Wpos[j + 1] + p1 * Wpos[POSD + j + 1] + bpos[j + 1];
        v.z = p0 * Wpos[j + 2] + p1 * Wpos[POSD + j + 2] + bpos[j + 2];
        v.w = p0 * Wpos[j + 3] + p1 * Wpos[POSD + j + 3] + bpos[j + 3];
    }
    ((float4*)g_h0)[tid] = v;
}

// ---------------- CSR by destination ----------------
__global__ void k_edge_count(const int* __restrict__ ei) {
    int e = blockIdx.x * blockDim.x + threadIdx.x;
    if (e >= ETOTE) return;
    int dst = (e < EE) ? ei[EE + e] : (e - EE);
    atomicAdd(&g_indeg[dst], 1);
}

__global__ void k_scanA() {
    __shared__ int s[256];
    int i = blockIdx.x * 256 + threadIdx.x;
    int v = (i < NN) ? g_indeg[i] : 0;
    s[threadIdx.x] = v;
    __syncthreads();
    for (int off = 1; off < 256; off <<= 1) {
        int t = (threadIdx.x >= off) ? s[threadIdx.x - off] : 0;
        __syncthreads();
        s[threadIdx.x] += t;
        __syncthreads();
    }
    if (i < NN) g_rowstart[i] = s[threadIdx.x] - v;
    if (threadIdx.x == 255) g_bsum[blockIdx.x] = s[255];
}

__global__ void k_scanB() {
    __shared__ int s[256];
    int t = threadIdx.x;
    int v = (t < 196) ? g_bsum[t] : 0;
    s[t] = v;
    __syncthreads();
    for (int off = 1; off < 256; off <<= 1) {
        int u = (t >= off) ? s[t - off] : 0;
        __syncthreads();
        s[t] += u;
        __syncthreads();
    }
    if (t < 196) g_bsum[t] = s[t] - v;
}

__global__ void k_scanC() {
    int i = blockIdx.x * 256 + threadIdx.x;
    if (i < NN) {
        int rs = g_rowstart[i] + g_bsum[blockIdx.x];
        g_rowstart[i] = rs;
        g_fillpos[i] = rs;
    }
    if (i == 0) g_rowstart[NN] = ETOTE;
}

__global__ void k_edge_fill(const int* __restrict__ ei) {
    int e = blockIdx.x * blockDim.x + threadIdx.x;
    if (e >= ETOTE) return;
    int src, dst;
    if (e < EE) { src = ei[e]; dst = ei[EE + e]; }
    else        { src = e - EE; dst = src; }
    int p = atomicAdd(&g_fillpos[dst], 1);
    g_csrsrc[p] = src;
}

// ---------------- bf16x3 split conversion (vectorized) ----------------
__global__ void k_convA(const float* __restrict__ A, int K, int Kp) {
    int idx = blockIdx.x * blockDim.x + threadIdx.x;      // over NN*K/4
    if (idx >= NN * (K / 4)) return;
    int n = idx / (K / 4), k = (idx - n * (K / 4)) * 4;
    float4 x = ((const float4*)A)[idx];
    __nv_bfloat162 h0 = __float22bfloat162_rn(make_float2(x.x, x.y));
    __nv_bfloat162 h1 = __float22bfloat162_rn(make_float2(x.z, x.w));
    float2 hlo0 = __bfloat1622float2(h0), hlo1 = __bfloat1622float2(h1);
    __nv_bfloat162 l0 = __float22bfloat162_rn(make_float2(x.x - hlo0.x, x.y - hlo0.y));
    __nv_bfloat162 l1 = __float22bfloat162_rn(make_float2(x.z - hlo1.x, x.w - hlo1.y));
    size_t base = (size_t)n * Kp + k;
    *(__nv_bfloat162*)(g_abf + base) = h0;
    *(__nv_bfloat162*)(g_abf + base + 2) = h1;
    *(__nv_bfloat162*)(g_abf + base + K) = l0;
    *(__nv_bfloat162*)(g_abf + base + K + 2) = l1;
    *(__nv_bfloat162*)(g_abf + base + 2 * K) = h0;
    *(__nv_bfloat162*)(g_abf + base + 2 * K + 2) = h1;
}

// layer-2 A conversion with fused BatchNorm + ELU
__global__ void k_convA_bn(const float* __restrict__ gamma, const float* __restrict__ beta) {
    int idx = blockIdx.x * blockDim.x + threadIdx.x;      // over NN*64
    if (idx >= NN * 64) return;
    int n = idx >> 6, k = (idx & 63) * 4;
    float4 v = ((const float4*)g_hagg)[idx];
    float y0 = gamma[k + 0] * (v.x - g_mean[k + 0]) * g_rstd[k + 0] + beta[k + 0];
    float y1 = gamma[k + 1] * (v.y - g_mean[k + 1]) * g_rstd[k + 1] + beta[k + 1];
    float y2 = gamma[k + 2] * (v.z - g_mean[k + 2]) * g_rstd[k + 2] + beta[k + 2];
    float y3 = gamma[k + 3] * (v.w - g_mean[k + 3]) * g_rstd[k + 3] + beta[k + 3];
    y0 = (y0 > 0.f) ? y0 : expm1f(y0);
    y1 = (y1 > 0.f) ? y1 : expm1f(y1);
    y2 = (y2 > 0.f) ? y2 : expm1f(y2);
    y3 = (y3 > 0.f) ? y3 : expm1f(y3);
    __nv_bfloat162 h0 = __float22bfloat162_rn(make_float2(y0, y1));
    __nv_bfloat162 h1 = __float22bfloat162_rn(make_float2(y2, y3));
    float2 f0 = __bfloat1622float2(h0), f1 = __bfloat1622float2(h1);
    __nv_bfloat162 l0 = __float22bfloat162_rn(make_float2(y0 - f0.x, y1 - f0.y));
    __nv_bfloat162 l1 = __float22bfloat162_rn(make_float2(y2 - f1.x, y3 - f1.y));
    size_t base = (size_t)n * 768 + k;
    *(__nv_bfloat162*)(g_abf + base) = h0;
    *(__nv_bfloat162*)(g_abf + base + 2) = h1;
    *(__nv_bfloat162*)(g_abf + base + 256) = l0;
    *(__nv_bfloat162*)(g_abf + base + 258) = l1;
    *(__nv_bfloat162*)(g_abf + base + 512) = h0;
    *(__nv_bfloat162*)(g_abf + base + 514) = h1;
}

// W' transposed to [n][k']: [W_hi | W_hi | W_lo], pad zero
__global__ void k_convW(const float* __restrict__ W, int K, int Kp) {
    int idx = blockIdx.x * blockDim.x + threadIdx.x;
    if (idx >= HCC * Kp) return;
    int n = idx / Kp, k = idx - n * Kp;
    __nv_bfloat16 v;
    if (k < K) {
        v = __float2bfloat16(W[(size_t)k * HCC + n]);
    } else if (k < 2 * K) {
        v = __float2bfloat16(W[(size_t)(k - K) * HCC + n]);
    } else if (k < 3 * K) {
        float x = W[(size_t)(k - 2 * K) * HCC + n];
        __nv_bfloat16 hi = __float2bfloat16(x);
        v = __float2bfloat16(x - __bfloat162float(hi));
    } else {
        v = __float2bfloat16(0.f);
    }
    g_wbf[idx] = v;
}

// ---------------- HMMA GEMM with fused alpha epilogue ----------------
// g_hlb[M,256] (bf16) = A'[M,KP] @ W'^T ; alpha logits accumulated into g_as/g_ad via atomics.
template<int KP>
__global__ void __launch_bounds__(256) k_gemm_mma(const float* __restrict__ asrc,
                                                  const float* __restrict__ adst) {
    __shared__ __nv_bfloat16 As[2][128][40];
    __shared__ __nv_bfloat16 Bs[2][128][40];
    const int tid = threadIdx.x;
    const int lane = tid & 31, wid = tid >> 5;
    const int wm = wid & 1, wn = wid >> 1;
    const int g = lane >> 2, tq = lane & 3;
    const int m0 = blockIdx.x * 128, n0 = blockIdx.y * 128;

    float acc[4][4][4];
    #pragma unroll
    for (int a = 0; a < 4; a++)
        #pragma unroll
        for (int b = 0; b < 4; b++)
            #pragma unroll
            for (int c = 0; c < 4; c++) acc[a][b][c] = 0.f;

    const int lr = tid >> 2;
    const int lc = tid & 3;
    const __nv_bfloat16* gA = g_abf + (size_t)m0 * KP;
    const __nv_bfloat16* gB = g_wbf + (size_t)n0 * KP;

    uint4 pa[2], pb[2];
    auto ld_chunk = [&](int k0) {
        #pragma unroll
        for (int i = 0; i < 2; i++) {
            int row = lr + i * 64;
            pa[i] = *(const uint4*)(gA + (size_t)row * KP + k0 + lc * 8);
            pb[i] = *(const uint4*)(gB + (size_t)row * KP + k0 + lc * 8);
        }
    };
    auto st_chunk = [&](int b) {
        #pragma unroll
        for (int i = 0; i < 2; i++) {
            int row = lr + i * 64;
            *(uint4*)&As[b][row][lc * 8] = pa[i];
            *(uint4*)&Bs[b][row][lc * 8] = pb[i];
        }
    };

    ld_chunk(0);
    st_chunk(0);
    __syncthreads();

    const int C = KP / 32;
    for (int c = 0; c < C; c++) {
        int cur = c & 1;
        if (c + 1 < C) ld_chunk((c + 1) * 32);
        #pragma unroll
        for (int ks = 0; ks < 2; ks++) {
            uint32_t af[4][4], bf[4][2];
            #pragma unroll
            for (int mt = 0; mt < 4; mt++) {
                int r = wm * 64 + mt * 16 + g;
                int cbase = ks * 16 + tq * 2;
                af[mt][0] = *(const uint32_t*)&As[cur][r][cbase];
                af[mt][1] = *(const uint32_t*)&As[cur][r + 8][cbase];
                af[mt][2] = *(const uint32_t*)&As[cur][r][cbase + 8];
                af[mt][3] = *(const uint32_t*)&As[cur][r + 8][cbase + 8];
            }
            #pragma unroll
            for (int nt = 0; nt < 4; nt++) {
                int r = wn * 32 + nt * 8 + g;
                int cbase = ks * 16 + tq * 2;
                bf[nt][0] = *(const uint32_t*)&Bs[cur][r][cbase];
                bf[nt][1] = *(const uint32_t*)&Bs[cur][r][cbase + 8];
            }
            #pragma unroll
            for (int mt = 0; mt < 4; mt++)
                #pragma unroll
                for (int nt = 0; nt < 4; nt++)
                    asm volatile(
                        "mma.sync.aligned.m16n8k16.row.col.f32.bf16.bf16.f32 "
                        "{%0,%1,%2,%3}, {%4,%5,%6,%7}, {%8,%9}, {%0,%1,%2,%3};\n"
                        : "+f"(acc[mt][nt][0]), "+f"(acc[mt][nt][1]),
                          "+f"(acc[mt][nt][2]), "+f"(acc[mt][nt][3])
                        : "r"(af[mt][0]), "r"(af[mt][1]), "r"(af[mt][2]), "r"(af[mt][3]),
                          "r"(bf[nt][0]), "r"(bf[nt][1]));
        }
        if (c + 1 < C) st_chunk(1 - cur);
        __syncthreads();
    }

    // ---- store bf16 features ----
    #pragma unroll
    for (int mt = 0; mt < 4; mt++) {
        int r0 = m0 + wm * 64 + mt * 16 + g;
        #pragma unroll
        for (int nt = 0; nt < 4; nt++) {
            int cc = n0 + wn * 32 + nt * 8 + tq * 2;
            if (r0 < NN)
                *(__nv_bfloat162*)&g_hlb[(size_t)r0 * HCC + cc] =
                    __float22bfloat162_rn(make_float2(acc[mt][nt][0], acc[mt][nt][1]));
            if (r0 + 8 < NN)
                *(__nv_bfloat162*)&g_hlb[(size_t)(r0 + 8) * HCC + cc] =
                    __float22bfloat162_rn(make_float2(acc[mt][nt][2], acc[mt][nt][3]));
        }
    }

    // ---- fused alpha logits: this warp's 32-col strip lies in exactly one head ----
    const int hh = (n0 + wn * 32) >> 6;
    #pragma unroll
    for (int mt = 0; mt < 4; mt++) {
        float ps0 = 0.f, pd0 = 0.f, ps1 = 0.f, pd1 = 0.f;
        #pragma unroll
        for (int nt = 0; nt < 4; nt++) {
            int cc = (n0 + wn * 32 + nt * 8 + tq * 2) & 63;  // channel within head
            float as0 = asrc[hh * CCD + cc], as1 = asrc[hh * CCD + cc + 1];
            float ad0 = adst[hh * CCD + cc], ad1 = adst[hh * CCD + cc + 1];
            ps0 += acc[mt][nt][0] * as0 + acc[mt][nt][1] * as1;
            pd0 += acc[mt][nt][0] * ad0 + acc[mt][nt][1] * ad1;
            ps1 += acc[mt][nt][2] * as0 + acc[mt][nt][3] * as1;
            pd1 += acc[mt][nt][2] * ad0 + acc[mt][nt][3] * ad1;
        }
        #pragma unroll
        for (int off = 1; off < 4; off <<= 1) {
            ps0 += __shfl_down_sync(0xFFFFFFFFu, ps0, off);
            pd0 += __shfl_down_sync(0xFFFFFFFFu, pd0, off);
            ps1 += __shfl_down_sync(0xFFFFFFFFu, ps1, off);
            pd1 += __shfl_down_sync(0xFFFFFFFFu, pd1, off);
        }
        if (tq == 0) {
            int r0 = m0 + wm * 64 + mt * 16 + g;
            if (r0 < NN) {
                atomicAdd(&g_as[r0 * HH + hh], ps0);
                atomicAdd(&g_ad[r0 * HH + hh], pd0);
            }
            if (r0 + 8 < NN) {
                atomicAdd(&g_as[(r0 + 8) * HH + hh], ps1);
                atomicAdd(&g_ad[(r0 + 8) * HH + hh], pd1);
            }
        }
    }
}

// ---------------- GAT gather: one warp per dst, bf16 messages (16B/edge-lane) ----------------
__global__ void k_gat_gather() {
    int gid = blockIdx.x * blockDim.x + threadIdx.x;
    int dst = gid >> 5;
    int lane = gid & 31;
    if (dst >= NN) return;
    int h = lane >> 3;
    float adh = g_ad[dst * HH + h];
    int beg = g_rowstart[dst], end = g_rowstart[dst + 1];

    float sum = 0.f;
    float acc[8];
    #pragma unroll
    for (int k = 0; k < 8; k++) acc[k] = 0.f;

    int e = beg;
    for (; e + 1 < end; e += 2) {
        int s0 = __ldg(&g_csrsrc[e]);
        int s1 = __ldg(&g_csrsrc[e + 1]);
        float v0 = __ldg(&g_as[s0 * HH + h]) + adh;
        float v1 = __ldg(&g_as[s1 * HH + h]) + adh;
        v0 = (v0 > 0.f) ? v0 : 0.2f * v0;
        v1 = (v1 > 0.f) ? v1 : 0.2f * v1;
        float w0 = __expf(v0);
        float w1 = __expf(v1);
        sum += w0 + w1;
        uint4 q0 = __ldg((const uint4*)(g_hlb + (size_t)s0 * HCC + lane * 8));
        uint4 q1 = __ldg((const uint4*)(g_hlb + (size_t)s1 * HCC + lane * 8));
        float2 a0 = __bfloat1622float2(*(__nv_bfloat162*)&q0.x);
        float2 a1 = __bfloat1622float2(*(__nv_bfloat162*)&q0.y);
        float2 a2 = __bfloat1622float2(*(__nv_bfloat162*)&q0.z);
        float2 a3 = __bfloat1622float2(*(__nv_bfloat162*)&q0.w);
        float2 b0 = __bfloat1622float2(*(__nv_bfloat162*)&q1.x);
        float2 b1 = __bfloat1622float2(*(__nv_bfloat162*)&q1.y);
        float2 b2 = __bfloat1622float2(*(__nv_bfloat162*)&q1.z);
        float2 b3 = __bfloat1622float2(*(__nv_bfloat162*)&q1.w);
        acc[0] += w0 * a0.x + w1 * b0.x;
        acc[1] += w0 * a0.y + w1 * b0.y;
        acc[2] += w0 * a1.x + w1 * b1.x;
        acc[3] += w0 * a1.y + w1 * b1.y;
        acc[4] += w0 * a2.x + w1 * b2.x;
        acc[5] += w0 * a2.y + w1 * b2.y;
        acc[6] += w0 * a3.x + w1 * b3.x;
        acc[7] += w0 * a3.y + w1 * b3.y;
    }
    if (e < end) {
        int s0 = __ldg(&g_csrsrc[e]);
        float v0 = __ldg(&g_as[s0 * HH + h]) + adh;
        v0 = (v0 > 0.f) ? v0 : 0.2f * v0;
        float w0 = __expf(v0);
        sum += w0;
        uint4 q0 = __ldg((const uint4*)(g_hlb + (size_t)s0 * HCC + lane * 8));
        float2 a0 = __bfloat1622float2(*(__nv_bfloat162*)&q0.x);
        float2 a1 = __bfloat1622float2(*(__nv_bfloat162*)&q0.y);
        float2 a2 = __bfloat1622float2(*(__nv_bfloat162*)&q0.z);
        float2 a3 = __bfloat1622float2(*(__nv_bfloat162*)&q0.w);
        acc[0] += w0 * a0.x; acc[1] += w0 * a0.y;
        acc[2] += w0 * a1.x; acc[3] += w0 * a1.y;
        acc[4] += w0 * a2.x; acc[5] += w0 * a2.y;
        acc[6] += w0 * a3.x; acc[7] += w0 * a3.y;
    }
    float rs = 1.f / sum;
    float4* op = (float4*)(g_hagg + (size_t)dst * HCC + lane * 8);
    op[0] = make_float4(acc[0] * rs, acc[1] * rs, acc[2] * rs, acc[3] * rs);
    op[1] = make_float4(acc[4] * rs, acc[5] * rs, acc[6] * rs, acc[7] * rs);
}

// ---------------- BatchNorm stats (+ re-zero alpha accumulators for next layer) ----------------
__global__ void k_bn_stats() {
    int gid = blockIdx.x * 256 + threadIdx.x;           // 64000 threads
    for (int i = gid; i < NN; i += 250 * 256) {
        float4 z = make_float4(0.f, 0.f, 0.f, 0.f);
        ((float4*)g_as)[i] = z;
        ((float4*)g_ad)[i] = z;
    }
    int c = threadIdx.x;
    int r0 = blockIdx.x * 200;
    float s = 0.f, sq = 0.f;
    for (int r = r0; r < r0 + 200; r++) {
        float v = g_hagg[(size_t)r * HCC + c];
        s += v;
        sq += v * v;
    }
    atomicAdd(&g_sum[c], (double)s);
    atomicAdd(&g_sumsq[c], (double)sq);
}

__global__ void k_bn_final() {
    int c = threadIdx.x;
    double m = g_sum[c] / (double)NN;
    double var = g_sumsq[c] / (double)NN - m * m;
    g_mean[c] = (float)m;
    g_rstd[c] = (float)(1.0 / sqrt(var + (double)BNEPS));
    g_sum[c] = 0.0;
    g_sumsq[c] = 0.0;
}

// ---------------- pooling (fused layer-2 BN + ELU) + FC ----------------
__global__ void k_pool(const float* __restrict__ gamma, const float* __restrict__ beta) {
    int b = blockIdx.x >> 2;
    int part = blockIdx.x & 3;
    int c = threadIdx.x;
    float ga = gamma[c], be = beta[c], m = g_mean[c], r_ = g_rstd[c];
    int st = g_starts[b], cnt = g_counts[b];
    int per = (cnt + 3) >> 2;
    int r0 = st + part * per;
    int r1 = st + cnt; if (r0 + per < r1) r1 = r0 + per;
    float s = 0.f;
    for (int r = r0; r < r1; r++) {
        float v = g_hagg[(size_t)r * HCC + c];
        float y = ga * (v - m) * r_ + be;
        s += (y > 0.f) ? y : expm1f(y);
    }
    atomicAdd(&g_pooled[b * HCC + c], s);
}

__global__ void k_fc(const float* __restrict__ Wfc, const float* __restrict__ bfc,
                     float* __restrict__ out) {
    int b = blockIdx.x;
    int j = threadIdx.x;
    float scale = 1.f / (float)g_counts[b];
    float s = 0.f;
    #pragma unroll 4
    for (int k = 0; k < HCC; k++) s += g_pooled[b * HCC + k] * Wfc[k * OUTD + j];
    out[b * OUTD + j] = s * scale + bfc[j];
}

// ---------------- launch ----------------
extern "C" void kernel_launch(void* const* d_in, const int* in_sizes, int n_in,
                              void* d_out, int out_size) {
    const float* x      = (const float*)d_in[0];
    const int*   ei     = (const int*)d_in[1];
    const int*   batch  = (const int*)d_in[2];
    const float* Wpos   = (const float*)d_in[3];
    const float* bpos   = (const float*)d_in[4];
    const float* W1     = (const float*)d_in[5];
    const float* asrc1  = (const float*)d_in[6];
    const float* adst1  = (const float*)d_in[7];
    const float* gamma1 = (const float*)d_in[9];
    const float* beta1  = (const float*)d_in[10];
    const float* W2     = (const float*)d_in[11];
    const float* asrc2  = (const float*)d_in[12];
    const float* adst2  = (const float*)d_in[13];
    const float* gamma2 = (const float*)d_in[15];
    const float* beta2  = (const float*)d_in[16];
    const float* Wfc    = (const float*)d_in[17];
    const float* bfc    = (const float*)d_in[18];
    float* out = (float*)d_out;

    const int NB = (NN + 255) / 256;
    const int EB = (ETOTE + 255) / 256;

    float* g_h0_p;  cudaGetSymbolAddress((void**)&g_h0_p,  g_h0);

    k_prep_zero<<<NB, 256>>>();
    k_count_nodes<<<NB, 256>>>(batch);
    k_graph_meta<<<1, 64>>>();
    k_build_h0<<<(NN * (ENHD / 4) + 255) / 256, 256>>>(x, batch, Wpos, bpos);

    k_edge_count<<<EB, 256>>>(ei);
    k_scanA<<<NB, 256>>>();
    k_scanB<<<1, 256>>>();
    k_scanC<<<NB, 256>>>();
    k_edge_fill<<<EB, 256>>>(ei);

    dim3 ggrid((NN + 127) / 128, 2);

    // layer 1 (alpha fused into GEMM epilogue)
    k_convW<<<(HCC * 448 + 255) / 256, 256>>>(W1, ENHD, 448);
    k_convA<<<(NN * (ENHD / 4) + 255) / 256, 256>>>(g_h0_p, ENHD, 448);
    k_gemm_mma<448><<<ggrid, 256>>>(asrc1, adst1);
    k_gat_gather<<<(NN * 32) / 256, 256>>>();
    k_bn_stats<<<250, 256>>>();        // also re-zeroes g_as/g_ad for layer 2
    k_bn_final<<<1, 256>>>();

    // layer 2 (BN1+ELU fused into convA_bn; alpha fused into GEMM epilogue)
    k_convW<<<(HCC * 768 + 255) / 256, 256>>>(W2, HCC, 768);
    k_convA_bn<<<(NN * 64 + 255) / 256, 256>>>(gamma1, beta1);
    k_gemm_mma<768><<<ggrid, 256>>>(asrc2, adst2);
    k_gat_gather<<<(NN * 32) / 256, 256>>>();
    k_bn_stats<<<250, 256>>>();
    k_bn_final<<<1, 256>>>();

    // pool (BN2+ELU fused) + fc
    k_pool<<<BB * 4, 256>>>(gamma2, beta2);
    k_fc<<<BB, 128>>>(Wfc, bfc, out);
}